// round 15
// baseline (speedup 1.0000x reference)
#include <cuda_runtime.h>
#include <cuda_bf16.h>
#include <math.h>

#define NNODE 16384
#define HEADS 8
#define DIM   64
#define HDIM  512
#define KBINS 40960

// ------------------------- device scratch (no allocs allowed) -------------------------
__device__ int   g_rank[2][NNODE];
__device__ int   g_order[16 * NNODE];
__device__ float g_h[NNODE * DIM];
__device__ float g_xn[NNODE * DIM];          // LN1(h), tf32-pre-rounded
__device__ float g_T[NNODE * HDIM];          // T = Xn @ M_h, tf32-pre-rounded
__device__ float g_hist[NNODE * 320];
__device__ float g_outr[16 * NNODE * DIM];   // R = P@X  [nh*8+h][node][d]
__device__ float g_lser[16 * NNODE];
__device__ float g_W2[4 * 16];               // [layer][h][c]
__device__ float g_M[4 * 8 * 64 * 64];       // [layer][head][d][e] = sum_c Wq[d,c]Wk[e,c]/8
__device__ float g_G[4 * 8 * 64 * 64];       // [layer][head][d][e] = Wv_h @ Ow_h (exact)
__device__ float g_t0[NNODE * 32];
__device__ float g_u [NNODE * 256];
__device__ float g_u2[NNODE * 256];
__device__ float g_t [NNODE * 32];
__device__ float g_part[128 * 32];

// sorting scratch
__device__ int r_base[2][NNODE];
__device__ int r_slot[2][NNODE];
__device__ int b_base[16][KBINS];
__device__ int b_slot[16][NNODE];

// ------------------------- tf32 / async helpers -------------------------
__device__ __forceinline__ unsigned f2tf(float f) {
    unsigned u;
    asm("cvt.rna.tf32.f32 %0, %1;" : "=r"(u) : "f"(f));
    return u;
}

__device__ __forceinline__ void mma_tf32(float c[4], unsigned a0, unsigned a1,
                                         unsigned a2, unsigned a3,
                                         unsigned b0, unsigned b1) {
    asm volatile(
        "mma.sync.aligned.m16n8k8.row.col.f32.tf32.tf32.f32 "
        "{%0,%1,%2,%3}, {%4,%5,%6,%7}, {%8,%9}, {%0,%1,%2,%3};"
        : "+f"(c[0]), "+f"(c[1]), "+f"(c[2]), "+f"(c[3])
        : "r"(a0), "r"(a1), "r"(a2), "r"(a3), "r"(b0), "r"(b1));
}

__device__ __forceinline__ void cp16(void* smem, const void* gmem) {
    unsigned sa = (unsigned)__cvta_generic_to_shared(smem);
    asm volatile("cp.async.cg.shared.global [%0], [%1], 16;" :: "r"(sa), "l"(gmem));
}

// ------------------------- coordinate ranks: one block per axis -------------------------
__device__ __forceinline__ int coord_bin(float c) {
    int u = (int)(c * 16384.0f);
    return min(16383, max(0, u));
}

__global__ void __launch_bounds__(1024) rankall_k(const float* __restrict__ coords) {
    extern __shared__ int hist[];           // 16384 ints (64 KB)
    __shared__ int ss[1024];
    int axis = blockIdx.x;
    int t = threadIdx.x;
    for (int i = t; i < NNODE; i += 1024) hist[i] = 0;
    __syncthreads();
    int   myu[16];
    float myc[16];
#pragma unroll
    for (int m = 0; m < 16; m++) {
        int i = t * 16 + m;
        float c = coords[i * 3 + axis];
        myc[m] = c;
        int u = coord_bin(c);
        myu[m] = u;
        atomicAdd(&hist[u], 1);
    }
    __syncthreads();
    // block scan over 16384 bins (16 per thread); zero hist as we go
    int s = 0;
#pragma unroll
    for (int m = 0; m < 16; m++) s += hist[t * 16 + m];
    ss[t] = s;
    __syncthreads();
    for (int d = 1; d < 1024; d <<= 1) {
        int v = (t >= d) ? ss[t - d] : 0;
        __syncthreads();
        ss[t] += v;
        __syncthreads();
    }
    int run = (t > 0) ? ss[t - 1] : 0;
#pragma unroll
    for (int m = 0; m < 16; m++) {
        int idx = t * 16 + m;
        int v = hist[idx];
        r_base[axis][idx] = run;
        run += v;
        hist[idx] = 0;                     // becomes the place-counter
    }
    __syncthreads();
    // place (hist restored to bin count afterwards)
#pragma unroll
    for (int m = 0; m < 16; m++) {
        int i = t * 16 + m;
        int u = myu[m];
        int slot = r_base[axis][u] + atomicAdd(&hist[u], 1);
        r_slot[axis][slot] = i;
    }
    __syncthreads();
    // rank within bin (stable: value, then index)
#pragma unroll
    for (int m = 0; m < 16; m++) {
        int i = t * 16 + m;
        int u = myu[m];
        float ci = myc[m];
        int b = r_base[axis][u], n = hist[u];
        int r = 0;
        for (int jj = 0; jj < n; jj++) {
            int jn = r_slot[axis][b + jj];
            float cj = coords[jn * 3 + axis];
            r += (int)((cj < ci) || (cj == ci && jn < i));
        }
        g_rank[axis][i] = b + r;
    }
}

// ------------------------- bucket order: one block per (nh,h) row -------------------------
__global__ void __launch_bounds__(1024) keyall_k(const float* __restrict__ regions) {
    extern __shared__ int kh[];             // 40960 ints (160 KB)
    __shared__ int ss[1024];
    int row = blockIdx.x;
    int nh = row >> 3, h = row & 7;
    float qe = 16384.0f / regions[nh * 16 + h];
    float qp = 16384.0f / regions[nh * 16 + 8 + h];
    int maxre = (int)floorf(16383.0f / qe) + 1;   // rank is a permutation of 0..16383
    int nb = (int)ceilf(log2f((float)maxre + 1.0f));
    int t = threadIdx.x;
    for (int i = t; i < KBINS; i += 1024) kh[i] = 0;
    __syncthreads();
    int mykey[16];
#pragma unroll
    for (int m = 0; m < 16; m++) {
        int i = t * 16 + m;
        int re = (int)floorf((float)g_rank[0][i] / qe) + 1;
        int rp = (int)floorf((float)g_rank[1][i] / qp) + 1;
        int key = (rp << nb) | re;
        mykey[m] = key;
        atomicAdd(&kh[key], 1);
    }
    __syncthreads();
    // block scan over 40960 bins (40 per thread); zero as we go
    int s = 0;
    for (int m = 0; m < 40; m++) s += kh[t * 40 + m];
    ss[t] = s;
    __syncthreads();
    for (int d = 1; d < 1024; d <<= 1) {
        int v = (t >= d) ? ss[t - d] : 0;
        __syncthreads();
        ss[t] += v;
        __syncthreads();
    }
    int run = (t > 0) ? ss[t - 1] : 0;
    for (int m = 0; m < 40; m++) {
        int idx = t * 40 + m;
        int v = kh[idx];
        b_base[row][idx] = run;
        run += v;
        kh[idx] = 0;
    }
    __syncthreads();
#pragma unroll
    for (int m = 0; m < 16; m++) {
        int i = t * 16 + m;
        int key = mykey[m];
        int slot = b_base[row][key] + atomicAdd(&kh[key], 1);
        b_slot[row][slot] = i;
    }
    __syncthreads();
#pragma unroll
    for (int m = 0; m < 16; m++) {
        int i = t * 16 + m;
        int key = mykey[m];
        int b = b_base[row][key], n = kh[key];
        int r = 0;
        for (int jj = 0; jj < n; jj++) r += (int)(b_slot[row][b + jj] < i);
        g_order[row * NNODE + b + r] = i;
    }
}

// ------------------------- RPE distance weights (all 4 layers) -------------------------
__global__ void w2all_k(const float* __restrict__ wrpe) {   // [4][512][16]
    __shared__ float sq[128];
    int l = blockIdx.x;
    const float* w = wrpe + (size_t)l * 512 * 16;
    int t = threadIdx.x;
    int h = t >> 4, m = t & 15;
    float s = 0.f;
    for (int d = 0; d < 64; d++) s += w[(h * 64 + d) * 16 + m];
    float om = s * (1.0f / 64.0f);
    sq[t] = om * om;
    __syncthreads();
    if (t < 16) {
        int hh = t >> 1, c = t & 1;
        float ww = 0.f;
        for (int kk = 0; kk < 8; kk++) ww += sq[hh * 16 + c * 8 + kk];
        g_W2[l * 16 + t] = ww;
    }
}

// ------------------------- M_h[d][e] = sum_c Wq[d,c] Wk[e,c] / 8 (exact fp32, NT) -------------------------
#define FMA16(av, bv, acc)                                                         \
    acc[0][0]+=av.x*bv.x; acc[0][1]+=av.x*bv.y; acc[0][2]+=av.x*bv.z; acc[0][3]+=av.x*bv.w; \
    acc[1][0]+=av.y*bv.x; acc[1][1]+=av.y*bv.y; acc[1][2]+=av.y*bv.z; acc[1][3]+=av.y*bv.w; \
    acc[2][0]+=av.z*bv.x; acc[2][1]+=av.z*bv.y; acc[2][2]+=av.z*bv.z; acc[2][3]+=av.z*bv.w; \
    acc[3][0]+=av.w*bv.x; acc[3][1]+=av.w*bv.y; acc[3][2]+=av.w*bv.z; acc[3][3]+=av.w*bv.w;

__global__ void __launch_bounds__(256) mh_k(const float* __restrict__ wq,
                                            const float* __restrict__ wk) {
    __shared__ float Aq[64 * 68];   // [d][c]
    __shared__ float Bk[64 * 68];   // [e][c]
    int bx = blockIdx.x;            // l*8 + h
    int l = bx >> 3, h = bx & 7;
    int tid = threadIdx.x;
#pragma unroll
    for (int it = 0; it < 4; it++) {
        int idx = tid + it * 256;
        int d = idx >> 4, c4 = (idx & 15) * 4;
        *(float4*)&Aq[d * 68 + c4] = *(const float4*)&wq[((size_t)(l * 64 + d)) * 512 + h * 64 + c4];
        *(float4*)&Bk[d * 68 + c4] = *(const float4*)&wk[((size_t)(l * 64 + d)) * 512 + h * 64 + c4];
    }
    __syncthreads();
    int tm = tid >> 4, tn = tid & 15;
    float acc[4][4] = {};
#pragma unroll 4
    for (int c = 0; c < 64; c++) {
        float4 av = make_float4(Aq[(tm * 4 + 0) * 68 + c], Aq[(tm * 4 + 1) * 68 + c],
                                Aq[(tm * 4 + 2) * 68 + c], Aq[(tm * 4 + 3) * 68 + c]);
        float4 bv = make_float4(Bk[(tn * 4 + 0) * 68 + c], Bk[(tn * 4 + 1) * 68 + c],
                                Bk[(tn * 4 + 2) * 68 + c], Bk[(tn * 4 + 3) * 68 + c]);
        FMA16(av, bv, acc)
    }
#pragma unroll
    for (int ii = 0; ii < 4; ii++)
#pragma unroll
        for (int jj = 0; jj < 4; jj++)
            g_M[(size_t)bx * 4096 + (tm * 4 + ii) * 64 + tn * 4 + jj] = 0.125f * acc[ii][jj];
}

// ------------------------- G_h = Wv_h @ Ow_h (exact, NN) -------------------------
__global__ void __launch_bounds__(256) gw_k(const float* __restrict__ wv,
                                            const float* __restrict__ ow) {
    __shared__ float Av[64 * 68];   // [d][c]
    __shared__ float Bo[64 * 68];   // [c][e]
    int bx = blockIdx.x;            // l*8 + h
    int l = bx >> 3, h = bx & 7;
    int tid = threadIdx.x;
#pragma unroll
    for (int it = 0; it < 4; it++) {
        int idx = tid + it * 256;
        int r = idx >> 4, c4 = (idx & 15) * 4;
        *(float4*)&Av[r * 68 + c4] = *(const float4*)&wv[((size_t)(l * 64 + r)) * 512 + h * 64 + c4];
        *(float4*)&Bo[r * 68 + c4] = *(const float4*)&ow[((size_t)(l * 512 + h * 64 + r)) * 64 + c4];
    }
    __syncthreads();
    int tm = tid >> 4, tn = tid & 15;
    float acc[4][4] = {};
#pragma unroll 4
    for (int c = 0; c < 64; c++) {
        float4 av = make_float4(Av[(tm * 4 + 0) * 68 + c], Av[(tm * 4 + 1) * 68 + c],
                                Av[(tm * 4 + 2) * 68 + c], Av[(tm * 4 + 3) * 68 + c]);
        float4 bv = *(const float4*)&Bo[c * 68 + tn * 4];
        FMA16(av, bv, acc)
    }
#pragma unroll
    for (int ii = 0; ii < 4; ii++)
#pragma unroll
        for (int jj = 0; jj < 4; jj++)
            g_G[(size_t)bx * 4096 + (tm * 4 + ii) * 64 + tn * 4 + jj] = acc[ii][jj];
}

// ------------------------- shared LN helper; writes tf32-pre-rounded output -------------------------
__device__ __forceinline__ void ln64_smem(const float* Xs, float (*redA)[4],
                                          const float* g, const float* b,
                                          float* dst, int row0, int tid) {
    int tr = tid >> 2, tp = tid & 3;
    float s = 0.f;
    for (int c = tp * 16; c < tp * 16 + 16; c++) s += Xs[tr * 68 + c];
    redA[tr][tp] = s;
    __syncthreads();
    float mu = (redA[tr][0] + redA[tr][1] + redA[tr][2] + redA[tr][3]) * (1.0f / 64.0f);
    __syncthreads();
    float vs = 0.f;
    for (int c = tp * 16; c < tp * 16 + 16; c++) {
        float d = Xs[tr * 68 + c] - mu;
        vs += d * d;
    }
    redA[tr][tp] = vs;
    __syncthreads();
    float var = (redA[tr][0] + redA[tr][1] + redA[tr][2] + redA[tr][3]) * (1.0f / 64.0f);
    float rs = rsqrtf(var + 1e-5f);
    for (int c = tp * 16; c < tp * 16 + 16; c++) {
        float vv = (Xs[tr * 68 + c] - mu) * rs * g[c] + b[c];
        dst[(size_t)(row0 + tr) * 64 + c] = __uint_as_float(f2tf(vv));
    }
}

// ------------------------- fused feat encoder + LN1(layer0) (exact FFMA) -------------------------
__global__ void __launch_bounds__(256) ffe_k(
    const float* __restrict__ x,
    const float* __restrict__ W1, const float* __restrict__ b1,
    const float* __restrict__ W2, const float* __restrict__ b2,
    const float* __restrict__ lng, const float* __restrict__ lnb)
{
    __shared__ float Xs16[64 * 17];
    __shared__ float W1s[16 * 68];
    __shared__ float Ts[64 * 68];
    __shared__ float W2s[64 * 68];
    __shared__ float redA[64][4];
    int tid = threadIdx.x;
    int row0 = blockIdx.x * 64;
    {
        int r = tid >> 2, c4 = (tid & 3) * 4;
        float4 xv = *(const float4*)&x[(size_t)(row0 + r) * 16 + c4];
        Xs16[r * 17 + c4 + 0] = xv.x; Xs16[r * 17 + c4 + 1] = xv.y;
        Xs16[r * 17 + c4 + 2] = xv.z; Xs16[r * 17 + c4 + 3] = xv.w;
    }
    if (tid < 16 * 16) {
        int r = tid >> 4, c4 = (tid & 15) * 4;
        *(float4*)&W1s[r * 68 + c4] = *(const float4*)&W1[(size_t)r * 64 + c4];
    }
#pragma unroll
    for (int it = 0; it < 4; it++) {
        int idx = tid + it * 256;
        int r = idx >> 4, c4 = (idx & 15) * 4;
        *(float4*)&W2s[r * 68 + c4] = *(const float4*)&W2[(size_t)r * 64 + c4];
    }
    __syncthreads();
    int tm = tid >> 4, tn = tid & 15;
    float acc[4][4] = {};
#pragma unroll
    for (int kk = 0; kk < 16; kk++) {
        float4 av = make_float4(Xs16[(tm * 4 + 0) * 17 + kk], Xs16[(tm * 4 + 1) * 17 + kk],
                                Xs16[(tm * 4 + 2) * 17 + kk], Xs16[(tm * 4 + 3) * 17 + kk]);
        float4 bv = *(const float4*)&W1s[kk * 68 + tn * 4];
        FMA16(av, bv, acc)
    }
#pragma unroll
    for (int ii = 0; ii < 4; ii++)
#pragma unroll
        for (int jj = 0; jj < 4; jj++)
            Ts[(tm * 4 + ii) * 68 + tn * 4 + jj] = fmaxf(acc[ii][jj] + b1[tn * 4 + jj], 0.f);
    __syncthreads();
    float acc2[4][4] = {};
#pragma unroll 8
    for (int kk = 0; kk < 64; kk++) {
        float4 av = make_float4(Ts[(tm * 4 + 0) * 68 + kk], Ts[(tm * 4 + 1) * 68 + kk],
                                Ts[(tm * 4 + 2) * 68 + kk], Ts[(tm * 4 + 3) * 68 + kk]);
        float4 bv = *(const float4*)&W2s[kk * 68 + tn * 4];
        FMA16(av, bv, acc2)
    }
    __syncthreads();
#pragma unroll
    for (int ii = 0; ii < 4; ii++) {
        int r = row0 + tm * 4 + ii;
#pragma unroll
        for (int jj = 0; jj < 4; jj++) {
            int c = tn * 4 + jj;
            float vv = acc2[ii][jj] + b2[c];
            g_h[(size_t)r * 64 + c] = vv;
            g_hist[(size_t)r * 320 + c] = vv;
            W2s[(tm * 4 + ii) * 68 + c] = vv;   // stage for LN
        }
    }
    __syncthreads();
    ln64_smem(W2s, redA, lng, lnb, (float*)g_xn, row0, tid);
}

// ------------------------- T = Xn @ M_h  (all nodes, per head), pre-rounded output -------------------------
__global__ void __launch_bounds__(256) tq_k(const float* __restrict__ Mbase) {
    __shared__ unsigned As[64 * 68];
    __shared__ unsigned Bs[64 * 68];
    int tid = threadIdx.x;
    int row0 = blockIdx.x * 64, h = blockIdx.y;
    const float* Mg = Mbase + (size_t)h * 4096;
#pragma unroll
    for (int it = 0; it < 4; it++) {
        int idx = tid + it * 256;
        int r = idx >> 4, c4 = (idx & 15) * 4;
        cp16(&As[r * 68 + c4], &g_xn[(size_t)(row0 + r) * 64 + c4]);   // pre-rounded
        float4 bv = *(const float4*)&Mg[r * 64 + c4];
        Bs[r * 68 + c4 + 0] = f2tf(bv.x); Bs[r * 68 + c4 + 1] = f2tf(bv.y);
        Bs[r * 68 + c4 + 2] = f2tf(bv.z); Bs[r * 68 + c4 + 3] = f2tf(bv.w);
    }
    asm volatile("cp.async.commit_group;");
    asm volatile("cp.async.wait_group 0;");
    __syncthreads();
    int wid = tid >> 5, lane = tid & 31;
    int g = lane >> 2, t = lane & 3;
    int r0 = (wid & 3) * 16, c0 = (wid >> 2) * 32;
    float acc[4][4] = {};
#pragma unroll
    for (int ks = 0; ks < 8; ks++) {
        int k0 = ks * 8;
        unsigned a0 = As[(r0 + g) * 68 + k0 + t];
        unsigned a1 = As[(r0 + g + 8) * 68 + k0 + t];
        unsigned a2 = As[(r0 + g) * 68 + k0 + t + 4];
        unsigned a3 = As[(r0 + g + 8) * 68 + k0 + t + 4];
#pragma unroll
        for (int nt = 0; nt < 4; nt++) {
            int n = c0 + nt * 8 + g;
            unsigned b0 = Bs[(k0 + t) * 68 + n];
            unsigned b1 = Bs[(k0 + t + 4) * 68 + n];
            mma_tf32(acc[nt], a0, a1, a2, a3, b0, b1);
        }
    }
#pragma unroll
    for (int nt = 0; nt < 4; nt++)
#pragma unroll
        for (int cr = 0; cr < 4; cr++) {
            int r = row0 + r0 + g + (cr >> 1) * 8;
            int c = c0 + nt * 8 + 2 * t + (cr & 1);
            g_T[(size_t)r * 512 + h * 64 + c] = __uint_as_float(f2tf(acc[nt][cr]));
        }
}

// ------------------------- attention: single bucket/block (R12 config) -------------------------
__global__ void __launch_bounds__(256) attn_k(
    const float* __restrict__ coords, const float* __restrict__ W2row)
{
    __shared__ unsigned Xs[64 * 68];   // X tf32
    __shared__ unsigned Ts[64 * 68];   // T tf32 -> S float / P tf32 [j][i]
    __shared__ int   nd[64];
    __shared__ float cx[64], cy[64], redm[4][64], reds[4][64];

    int tid = threadIdx.x;
    int blk = blockIdx.x, h = blockIdx.y, nh = blockIdx.z;
    int row = nh * 8 + h;
    const int* ord = g_order + row * NNODE + blk * 64;
    if (tid < 64) {
        int nn = ord[tid];
        nd[tid] = nn;
        cx[tid] = coords[nn * 3 + 0];
        cy[tid] = coords[nn * 3 + 1];
    }
    __syncthreads();

#pragma unroll
    for (int it = 0; it < 4; it++) {
        int idx = tid + it * 256;               // 0..1023
        int i = idx >> 4, q = (idx & 15) * 4;
        size_t nb = (size_t)nd[i];
        cp16(&Xs[i * 68 + q], &g_xn[nb * 64 + q]);
        cp16(&Ts[i * 68 + q], &g_T[nb * 512 + h * 64 + q]);
    }
    asm volatile("cp.async.commit_group;");
    asm volatile("cp.async.wait_group 0;");
    __syncthreads();

    int wid = tid >> 5, lane = tid & 31;
    int g = lane >> 2, t = lane & 3;
    int r0 = (wid & 3) * 16, c0 = (wid >> 2) * 32;

    // S = T @ X^T (+RPE) in registers
    float acc[4][4] = {};
#pragma unroll
    for (int ks = 0; ks < 8; ks++) {
        int k0 = ks * 8;
        unsigned a0 = Ts[(r0 + g) * 68 + k0 + t];
        unsigned a1 = Ts[(r0 + g + 8) * 68 + k0 + t];
        unsigned a2 = Ts[(r0 + g) * 68 + k0 + t + 4];
        unsigned a3 = Ts[(r0 + g + 8) * 68 + k0 + t + 4];
#pragma unroll
        for (int nt = 0; nt < 4; nt++) {
            int j = c0 + nt * 8 + g;
            unsigned b0 = Xs[j * 68 + k0 + t];
            unsigned b1 = Xs[j * 68 + k0 + t + 4];
            mma_tf32(acc[nt], a0, a1, a2, a3, b0, b1);
        }
    }
    float W0 = W2row[h * 2 + 0], W1 = W2row[h * 2 + 1];
    __syncthreads();   // all reads of Ts done; reuse as S

    float* Sf = (float*)Ts;
#pragma unroll
    for (int nt = 0; nt < 4; nt++) {
        int j0 = c0 + nt * 8 + 2 * t;
#pragma unroll
        for (int cr = 0; cr < 4; cr++) {
            int i = r0 + g + (cr >> 1) * 8;
            int j = j0 + (cr & 1);
            float dx = cx[i] - cx[j], dy = cy[i] - cy[j];
            Sf[j * 68 + i] = acc[nt][cr] - W0 * dx * dx - W1 * dy * dy;
        }
    }
    __syncthreads();

    int ci = tid & 63, seg = tid >> 6;
    float ml = -3.0e38f;
#pragma unroll
    for (int jj = 0; jj < 16; jj++) ml = fmaxf(ml, Sf[(seg * 16 + jj) * 68 + ci]);
    redm[seg][ci] = ml;
    __syncthreads();
    float mm = fmaxf(fmaxf(redm[0][ci], redm[1][ci]), fmaxf(redm[2][ci], redm[3][ci]));
    float ev[16];
    float sl = 0.f;
#pragma unroll
    for (int jj = 0; jj < 16; jj++) {
        float e = __expf(Sf[(seg * 16 + jj) * 68 + ci] - mm);
        ev[jj] = e;
        sl += e;
    }
    reds[seg][ci] = sl;
    __syncthreads();
    float ssum = reds[0][ci] + reds[1][ci] + reds[2][ci] + reds[3][ci];
    float inv = 1.0f / ssum;
    if (seg == 0) g_lser[row * NNODE + nd[ci]] = mm + __logf(ssum);
    unsigned* Ps = Ts;
#pragma unroll
    for (int jj = 0; jj < 16; jj++)
        Ps[(seg * 16 + jj) * 68 + ci] = f2tf(ev[jj] * inv);
    __syncthreads();

    // R = P @ X
    float racc[4][4] = {};
#pragma unroll
    for (int ks = 0; ks < 8; ks++) {
        int k0 = ks * 8;
        unsigned a0 = Ps[(k0 + t) * 68 + r0 + g];
        unsigned a1 = Ps[(k0 + t) * 68 + r0 + g + 8];
        unsigned a2 = Ps[(k0 + t + 4) * 68 + r0 + g];
        unsigned a3 = Ps[(k0 + t + 4) * 68 + r0 + g + 8];
#pragma unroll
        for (int nt = 0; nt < 4; nt++) {
            int n = c0 + nt * 8 + g;
            unsigned b0 = Xs[(k0 + t) * 68 + n];
            unsigned b1 = Xs[(k0 + t + 4) * 68 + n];
            mma_tf32(racc[nt], a0, a1, a2, a3, b0, b1);
        }
    }
#pragma unroll
    for (int nt = 0; nt < 4; nt++) {
        int d0 = c0 + nt * 8 + 2 * t;
        int iA = r0 + g, iB = r0 + g + 8;
        *(float2*)&g_outr[((size_t)row * NNODE + nd[iA]) * 64 + d0] =
            make_float2(racc[nt][0], racc[nt][1]);
        *(float2*)&g_outr[((size_t)row * NNODE + nd[iB]) * 64 + d0] =
            make_float2(racc[nt][2], racc[nt][3]);
    }
}

// ------------------------- fused epilogue: outproj + LN2 + FFN + resid + hist + LN1(next) ----------
__global__ void __launch_bounds__(256) epi_k(
    const float* __restrict__ gG, const float* __restrict__ ob,
    const float* __restrict__ lg2, const float* __restrict__ lb2,
    const float* __restrict__ W1, const float* __restrict__ b1,
    const float* __restrict__ W2, const float* __restrict__ b2,
    float* __restrict__ hist,
    const float* __restrict__ lnn_g, const float* __restrict__ lnn_b)
{
    extern __shared__ unsigned dyn[];
    unsigned* AsU = dyn;
    unsigned* BsU = dyn + 64 * 68;
    float*    Hs  = (float*)(dyn + 2 * 64 * 68);
    __shared__ float redA[64][4];
    __shared__ float w0s[64], w1s[64];
    float* As = (float*)AsU;
    float* Ws = (float*)BsU;
    int tid = threadIdx.x;
    int row0 = blockIdx.x * 64;
    int wid = tid >> 5, lane = tid & 31;
    int g = lane >> 2, t = lane & 3;
    int r0 = (wid & 3) * 16, c0 = (wid >> 2) * 32;

    float acc[4][4] = {};
    for (int h = 0; h < 8; h++) {
        __syncthreads();
        if (tid < 64) {
            int node = row0 + tid;
            float l0 = g_lser[h * NNODE + node];
            float l1 = g_lser[(8 + h) * NNODE + node];
            float m = fmaxf(l0, l1);
            float e0 = __expf(l0 - m), e1 = __expf(l1 - m);
            float inv = 1.0f / (e0 + e1);
            w0s[tid] = e0 * inv;
            w1s[tid] = e1 * inv;
        }
        __syncthreads();
#pragma unroll
        for (int it = 0; it < 4; it++) {
            int idx = tid + it * 256;
            int r = idx >> 4, c4 = (idx & 15) * 4;
            int node = row0 + r;
            float4 o0 = *(const float4*)&g_outr[((size_t)h * NNODE + node) * 64 + c4];
            float4 o1 = *(const float4*)&g_outr[((size_t)(8 + h) * NNODE + node) * 64 + c4];
            float w0 = w0s[r], w1 = w1s[r];
            AsU[r * 68 + c4 + 0] = f2tf(w0 * o0.x + w1 * o1.x);
            AsU[r * 68 + c4 + 1] = f2tf(w0 * o0.y + w1 * o1.y);
            AsU[r * 68 + c4 + 2] = f2tf(w0 * o0.z + w1 * o1.z);
            AsU[r * 68 + c4 + 3] = f2tf(w0 * o0.w + w1 * o1.w);
            float4 bv = *(const float4*)&gG[(size_t)h * 4096 + r * 64 + c4];
            BsU[r * 68 + c4 + 0] = f2tf(bv.x); BsU[r * 68 + c4 + 1] = f2tf(bv.y);
            BsU[r * 68 + c4 + 2] = f2tf(bv.z); BsU[r * 68 + c4 + 3] = f2tf(bv.w);
        }
        __syncthreads();
#pragma unroll
        for (int ks = 0; ks < 8; ks++) {
            int k0 = ks * 8;
            unsigned a0 = AsU[(r0 + g) * 68 + k0 + t];
            unsigned a1 = AsU[(r0 + g + 8) * 68 + k0 + t];
            unsigned a2 = AsU[(r0 + g) * 68 + k0 + t + 4];
            unsigned a3 = AsU[(r0 + g + 8) * 68 + k0 + t + 4];
#pragma unroll
            for (int nt = 0; nt < 4; nt++) {
                int n = c0 + nt * 8 + g;
                unsigned b0 = BsU[(k0 + t) * 68 + n];
                unsigned b1 = BsU[(k0 + t + 4) * 68 + n];
                mma_tf32(acc[nt], a0, a1, a2, a3, b0, b1);
            }
        }
    }
    __syncthreads();
#pragma unroll
    for (int nt = 0; nt < 4; nt++) {
#pragma unroll
        for (int cr = 0; cr < 4; cr++) {
            int rl = r0 + g + (cr >> 1) * 8;
            int ccol = c0 + nt * 8 + 2 * t + (cr & 1);
            Hs[rl * 68 + ccol] = acc[nt][cr] + ob[ccol] + g_h[(size_t)(row0 + rl) * 64 + ccol];
        }
    }
    __syncthreads();

    {
        int tr = tid >> 2, tp = tid & 3;
        float s = 0.f;
        for (int c = tp * 16; c < tp * 16 + 16; c++) s += Hs[tr * 68 + c];
        redA[tr][tp] = s;
        __syncthreads();
        float mu = (redA[tr][0] + redA[tr][1] + redA[tr][2] + redA[tr][3]) * (1.0f / 64.0f);
        __syncthreads();
        float vs = 0.f;
        for (int c = tp * 16; c < tp * 16 + 16; c++) {
            float d = Hs[tr * 68 + c] - mu;
            vs += d * d;
        }
        redA[tr][tp] = vs;
        __syncthreads();
        float var = (redA[tr][0] + redA[tr][1] + redA[tr][2] + redA[tr][3]) * (1.0f / 64.0f);
        float rs = rsqrtf(var + 1e-5f);
        for (int c = tp * 16; c < tp * 16 + 16; c++)
            As[tr * 68 + c] = (Hs[tr * 68 + c] - mu) * rs * lg2[c] + lb2[c];
    }
#pragma unroll
    for (int it = 0; it < 4; it++) {
        int idx = tid + it * 256;
        int r = idx >> 4, c4 = (idx & 15) * 4;
        *(float4*)&Ws[r * 68 + c4] = *(const float4*)&W1[(size_t)r * 64 + c4];
    }
    __syncthreads();

    int tm = tid >> 4, tn = tid & 15;
    float ac1[4][4] = {};
#pragma unroll 8
    for (int kk = 0; kk < 64; kk++) {
        float4 bv = *(const float4*)&Ws[kk * 68 + tn * 4];
        float4 av = make_float4(As[(tm * 4 + 0) * 68 + kk], As[(tm * 4 + 1) * 68 + kk],
                                As[(tm * 4 + 2) * 68 + kk], As[(tm * 4 + 3) * 68 + kk]);
        FMA16(av, bv, ac1)
    }
    __syncthreads();
#pragma unroll
    for (int ii = 0; ii < 4; ii++)
#pragma unroll
        for (int jj = 0; jj < 4; jj++)
            As[(tm * 4 + ii) * 68 + tn * 4 + jj] = fmaxf(ac1[ii][jj] + b1[tn * 4 + jj], 0.f);
#pragma unroll
    for (int it = 0; it < 4; it++) {
        int idx = tid + it * 256;
        int r = idx >> 4, c4 = (idx & 15) * 4;
        *(float4*)&Ws[r * 68 + c4] = *(const float4*)&W2[(size_t)r * 64 + c4];
    }
    __syncthreads();
    float ac2[4][4] = {};
#pragma unroll 8
    for (int kk = 0; kk < 64; kk++) {
        float4 bv = *(const float4*)&Ws[kk * 68 + tn * 4];
        float4 av = make_float4(As[(tm * 4 + 0) * 68 + kk], As[(tm * 4 + 1) * 68 + kk],
                                As[(tm * 4 + 2) * 68 + kk], As[(tm * 4 + 3) * 68 + kk]);
        FMA16(av, bv, ac2)
    }
    __syncthreads();
#pragma unroll
    for (int ii = 0; ii < 4; ii++) {
        int r = row0 + tm * 4 + ii;
        int rl = tm * 4 + ii;
#pragma unroll
        for (int jj = 0; jj < 4; jj++) {
            int c = tn * 4 + jj;
            float vv = ac2[ii][jj] + b2[c] + Hs[rl * 68 + c];
            g_h[(size_t)r * 64 + c] = vv;
            hist[(size_t)r * 320 + c] = vv;
            As[rl * 68 + c] = vv;
        }
    }
    if (lnn_g) {
        __syncthreads();
        ln64_smem(As, redA, lnn_g, lnn_b, (float*)g_xn, row0, tid);
    }
}

// ------------------------- scalar FFMA SGEMM (head) -------------------------
__global__ void __launch_bounds__(256) gemm_k(
    const float* __restrict__ A, const float* __restrict__ B, float* __restrict__ C,
    const float* __restrict__ bias, const float* __restrict__ resid,
    int M, int N, int K, int act)
{
    __shared__ float As[16][68];
    __shared__ float Bs[16][68];
    int tid = threadIdx.x;
    int row0 = blockIdx.x * 64, col0 = blockIdx.y * 64;
    int tm = tid >> 4, tn = tid & 15;
    int arow = tid >> 2, ac = tid & 3;
    int bk = tid >> 4, bn = tid & 15;
    float acc[4][4] = {};
    for (int k0 = 0; k0 < K; k0 += 16) {
        float4 a = *(const float4*)&A[(size_t)(row0 + arow) * K + k0 + ac * 4];
        As[ac * 4 + 0][arow] = a.x; As[ac * 4 + 1][arow] = a.y;
        As[ac * 4 + 2][arow] = a.z; As[ac * 4 + 3][arow] = a.w;
        int bcol = col0 + bn * 4;
        float4 bv = make_float4(0.f, 0.f, 0.f, 0.f);
        if (bcol < N) bv = *(const float4*)&B[(size_t)(k0 + bk) * N + bcol];
        *(float4*)&Bs[bk][bn * 4] = bv;
        __syncthreads();
#pragma unroll
        for (int kk = 0; kk < 16; kk++) {
            float4 av = *(const float4*)&As[kk][tm * 4];
            float4 bw = *(const float4*)&Bs[kk][tn * 4];
            FMA16(av, bw, acc)
        }
        __syncthreads();
    }
#pragma unroll
    for (int ii = 0; ii < 4; ii++) {
        int r = row0 + tm * 4 + ii;
#pragma unroll
        for (int jj = 0; jj < 4; jj++) {
            int ccol = col0 + tn * 4 + jj;
            if (ccol < N) {
                float vv = acc[ii][jj];
                if (bias) vv += bias[ccol];
                if (act == 1) vv = fmaxf(vv, 0.f);
                else if (act == 2) vv = tanhf(vv);
                if (resid) vv += resid[(size_t)r * N + ccol];
                C[(size_t)r * N + ccol] = vv;
            }
        }
    }
}

// ------------------------- LayerNorm 256 + tanh, warp per row -------------------------
__global__ void ln256w_k(const float* __restrict__ in, float* __restrict__ out,
                         const float* __restrict__ g, const float* __restrict__ b) {
    int w = threadIdx.x >> 5, lane = threadIdx.x & 31;
    int row = blockIdx.x * 8 + w;
    const float* xr = in + (size_t)row * 256;
    float x[8];
    float s = 0.f;
#pragma unroll
    for (int m = 0; m < 8; m++) { x[m] = xr[lane + 32 * m]; s += x[m]; }
    for (int o = 16; o; o >>= 1) s += __shfl_xor_sync(0xffffffffu, s, o);
    float mu = s * (1.0f / 256.0f);
    float vs = 0.f;
#pragma unroll
    for (int m = 0; m < 8; m++) { float d = x[m] - mu; vs += d * d; }
    for (int o = 16; o; o >>= 1) vs += __shfl_xor_sync(0xffffffffu, vs, o);
    float rs = rsqrtf(vs * (1.0f / 256.0f) + 1e-5f);
#pragma unroll
    for (int m = 0; m < 8; m++) {
        int c = lane + 32 * m;
        out[(size_t)row * 256 + c] = tanhf((x[m] - mu) * rs * g[c] + b[c]);
    }
}

// ------------------------- reductions + final projection -------------------------
__global__ void red1_k(const float* __restrict__ t) {
    __shared__ float sm[256];
    int blk = blockIdx.x, tid = threadIdx.x;
    int col = tid & 31, r0 = tid >> 5;
    float s = 0.f;
    for (int r = r0; r < 128; r += 8) s += t[(size_t)(blk * 128 + r) * 32 + col];
    sm[tid] = s;
    __syncthreads();
    for (int s2 = 4; s2; s2 >>= 1) {
        if (r0 < s2) sm[tid] += sm[tid + s2 * 32];
        __syncthreads();
    }
    if (r0 == 0) g_part[blk * 32 + col] = sm[col];
}

__global__ void red2_k(const float* __restrict__ pw, const float* __restrict__ pb,
                       float* __restrict__ out) {
    __shared__ float mean[32];
    int t = threadIdx.x;
    if (t < 32) {
        float s = 0.f;
        for (int b = 0; b < 128; b++) s += g_part[b * 32 + t];
        mean[t] = s * (1.0f / 16384.0f);
    }
    __syncthreads();
    if (t < 32) {
        float s = pb[t];
        for (int c = 0; c < 32; c++) s += mean[c] * pw[c * 32 + t];
        out[t] = s;
    }
}

// ------------------------- host orchestration -------------------------
extern "C" void kernel_launch(void* const* d_in, const int* in_sizes, int n_in,
                              void* d_out, int out_size)
{
    const float* x      = (const float*)d_in[0];
    const float* coords = (const float*)d_in[1];
    const float* regions= (const float*)d_in[3];
    const float* fe_w1  = (const float*)d_in[4];
    const float* fe_b1  = (const float*)d_in[5];
    const float* fe_w2  = (const float*)d_in[6];
    const float* fe_b2  = (const float*)d_in[7];
    const float* ln1_g  = (const float*)d_in[8];
    const float* ln1_b  = (const float*)d_in[9];
    const float* wq     = (const float*)d_in[10];
    const float* wk     = (const float*)d_in[11];
    const float* wv     = (const float*)d_in[12];
    const float* wrpe   = (const float*)d_in[13];
    const float* ow     = (const float*)d_in[14];
    const float* ob     = (const float*)d_in[15];
    const float* ln2_g  = (const float*)d_in[16];
    const float* ln2_b  = (const float*)d_in[17];
    const float* f1w    = (const float*)d_in[18];
    const float* f1b    = (const float*)d_in[19];
    const float* f2w    = (const float*)d_in[20];
    const float* f2b    = (const float*)d_in[21];
    const float* Wcat   = (const float*)d_in[22];
    const float* m1w    = (const float*)d_in[23];
    const float* m1b    = (const float*)d_in[24];
    const float* mlng   = (const float*)d_in[25];
    const float* mlnb   = (const float*)d_in[26];
    const float* m2w    = (const float*)d_in[27];
    const float* m2b    = (const float*)d_in[28];
    const float* pw     = (const float*)d_in[29];
    const float* pb     = (const float*)d_in[30];
    float* out = (float*)d_out;

    cudaFuncSetAttribute(epi_k,    cudaFuncAttributeMaxDynamicSharedMemorySize, 52224);
    cudaFuncSetAttribute(rankall_k, cudaFuncAttributeMaxDynamicSharedMemorySize, 65536);
    cudaFuncSetAttribute(keyall_k,  cudaFuncAttributeMaxDynamicSharedMemorySize, 163840);

    float *p_hist, *p_t0, *p_u, *p_u2, *p_t, *p_w2, *p_M, *p_G;
    cudaGetSymbolAddress((void**)&p_hist, g_hist);
    cudaGetSymbolAddress((void**)&p_t0,   g_t0);
    cudaGetSymbolAddress((void**)&p_u,    g_u);
    cudaGetSymbolAddress((void**)&p_u2,   g_u2);
    cudaGetSymbolAddress((void**)&p_t,    g_t);
    cudaGetSymbolAddress((void**)&p_w2,   g_W2);
    cudaGetSymbolAddress((void**)&p_M,    g_M);
    cudaGetSymbolAddress((void**)&p_G,    g_G);

    const int M = NNODE;

    // ---- bucket ordering: fully fused counting sorts ----
    rankall_k<<<2, 1024, 65536>>>(coords);
    keyall_k<<<16, 1024, 163840>>>(regions);
    w2all_k<<<4, 128>>>(wrpe);
    mh_k<<<32, 256>>>(wq, wk);
    gw_k<<<32, 256>>>(wv, ow);

    // feat encoder + LN1(layer 0)
    ffe_k<<<256, 256>>>(x, fe_w1, fe_b1, fe_w2, fe_b2, ln1_g, ln1_b);

    for (int l = 0; l < 4; l++) {
        tq_k<<<dim3(256, 8), 256>>>(p_M + (size_t)l * 8 * 4096);
        attn_k<<<dim3(256, 8, 2), 256>>>(coords, p_w2 + l * 16);
        const float* nlg = (l < 3) ? (ln1_g + (l + 1) * 64) : nullptr;
        const float* nlb = (l < 3) ? (ln1_b + (l + 1) * 64) : nullptr;
        epi_k<<<256, 256, 52224>>>(p_G + (size_t)l * 8 * 4096, ob + l * 64,
                                   ln2_g + l * 64, ln2_b + l * 64,
                                   f1w + (size_t)l * 64 * 64, f1b + l * 64,
                                   f2w + (size_t)l * 64 * 64, f2b + l * 64,
                                   p_hist + (l + 1) * 64, nlg, nlb);
    }

    gemm_k<<<dim3(256, 1), 256>>>(p_hist, Wcat, p_t0, nullptr, nullptr, M, 32, 320, 2);
    gemm_k<<<dim3(256, 4), 256>>>(p_t0, m1w, p_u, m1b, nullptr, M, 256, 32, 0);
    ln256w_k<<<2048, 256>>>(p_u, p_u2, mlng, mlnb);
    gemm_k<<<dim3(256, 1), 256>>>(p_u2, m2w, p_t, m2b, p_t0, M, 32, 256, 0);
    red1_k<<<128, 256>>>(p_t);
    red2_k<<<1, 256>>>(pw, pb, out);
}

// round 16
// speedup vs baseline: 1.1242x; 1.1242x over previous
#include <cuda_runtime.h>
#include <cuda_bf16.h>
#include <math.h>

#define NNODE 16384
#define HEADS 8
#define DIM   64
#define HDIM  512
#define KBINS 40960

// ------------------------- device scratch (no allocs allowed) -------------------------
__device__ int   g_rank[2][NNODE];
__device__ int   g_order[16 * NNODE];
__device__ float g_h[NNODE * DIM];
__device__ float g_xn[NNODE * DIM];          // LN1(h), tf32-pre-rounded
__device__ float g_T[NNODE * HDIM];          // T = Xn @ M_h, tf32-pre-rounded
__device__ float g_hist[NNODE * 320];
__device__ float g_outr[16 * NNODE * DIM];   // R = P@X  [nh*8+h][node][d]
__device__ float g_lser[16 * NNODE];
__device__ float g_W2[4 * 16];               // [layer][h][c]
__device__ float g_M[4 * 8 * 64 * 64];       // [layer][head][d][e] = sum_c Wq[d,c]Wk[e,c]/8
__device__ float g_G[4 * 8 * 64 * 64];       // [layer][head][d][e] = Wv_h @ Ow_h (tf32-pre-rounded)
__device__ float g_t0[NNODE * 32];
__device__ float g_u [NNODE * 256];
__device__ float g_u2[NNODE * 256];
__device__ float g_t [NNODE * 32];
__device__ float g_part[128 * 32];

// sorting scratch
__device__ int r_hist[2][NNODE];
__device__ int r_base[2][NNODE];
__device__ int r_cnt [2][NNODE];
__device__ int r_slot[2][NNODE];
__device__ int b_keys[16][NNODE];
__device__ int b_hist[16][KBINS];
__device__ int b_base[16][KBINS];
__device__ int b_cnt [16][KBINS];
__device__ int b_slot[16][NNODE];

// ------------------------- tf32 / async helpers -------------------------
__device__ __forceinline__ unsigned f2tf(float f) {
    unsigned u;
    asm("cvt.rna.tf32.f32 %0, %1;" : "=r"(u) : "f"(f));
    return u;
}

__device__ __forceinline__ void mma_tf32(float c[4], unsigned a0, unsigned a1,
                                         unsigned a2, unsigned a3,
                                         unsigned b0, unsigned b1) {
    asm volatile(
        "mma.sync.aligned.m16n8k8.row.col.f32.tf32.tf32.f32 "
        "{%0,%1,%2,%3}, {%4,%5,%6,%7}, {%8,%9}, {%0,%1,%2,%3};"
        : "+f"(c[0]), "+f"(c[1]), "+f"(c[2]), "+f"(c[3])
        : "r"(a0), "r"(a1), "r"(a2), "r"(a3), "r"(b0), "r"(b1));
}

__device__ __forceinline__ void cp16(void* smem, const void* gmem) {
    unsigned sa = (unsigned)__cvta_generic_to_shared(smem);
    asm volatile("cp.async.cg.shared.global [%0], [%1], 16;" :: "r"(sa), "l"(gmem));
}

// ------------------------- zero all counting scratch -------------------------
__global__ void zero_k() {
    int gid = blockIdx.x * 256 + threadIdx.x;
    int stride = gridDim.x * 256;
    for (int i = gid; i < 2 * NNODE; i += stride) { ((int*)r_hist)[i] = 0; ((int*)r_cnt)[i] = 0; }
    for (int i = gid; i < 16 * KBINS; i += stride) { ((int*)b_hist)[i] = 0; ((int*)b_cnt)[i] = 0; }
}

// ------------------------- coordinate ranks via counting -------------------------
__device__ __forceinline__ int coord_bin(float c) {
    int u = (int)(c * 16384.0f);
    return min(16383, max(0, u));
}

__global__ void rank_hist_k(const float* __restrict__ coords) {
    int axis = blockIdx.y;
    int i = blockIdx.x * 256 + threadIdx.x;
    int u = coord_bin(coords[i * 3 + axis]);
    atomicAdd(&r_hist[axis][u], 1);
}

__global__ void __launch_bounds__(1024) scan_k(const int* __restrict__ hist,
                                               int* __restrict__ base,
                                               int nbins, int rowstride) {
    __shared__ int ss[1024];
    int row = blockIdx.x;
    const int* h = hist + (size_t)row * rowstride;
    int* bs = base + (size_t)row * rowstride;
    int t = threadIdx.x;
    int chunk = (nbins + 1023) >> 10;
    int b0 = t * chunk;
    int s = 0;
    for (int m = 0; m < chunk; m++) { int idx = b0 + m; if (idx < nbins) s += h[idx]; }
    ss[t] = s;
    __syncthreads();
    for (int d = 1; d < 1024; d <<= 1) {
        int v = (t >= d) ? ss[t - d] : 0;
        __syncthreads();
        ss[t] += v;
        __syncthreads();
    }
    int run = (t > 0) ? ss[t - 1] : 0;
    for (int m = 0; m < chunk; m++) {
        int idx = b0 + m;
        if (idx < nbins) { bs[idx] = run; run += h[idx]; }
    }
}

__global__ void rank_place_k(const float* __restrict__ coords) {
    int axis = blockIdx.y;
    int i = blockIdx.x * 256 + threadIdx.x;
    int u = coord_bin(coords[i * 3 + axis]);
    int slot = r_base[axis][u] + atomicAdd(&r_cnt[axis][u], 1);
    r_slot[axis][slot] = i;
}

__global__ void rank_rank_k(const float* __restrict__ coords) {
    int axis = blockIdx.y;
    int i = blockIdx.x * 256 + threadIdx.x;
    float ci = coords[i * 3 + axis];
    int u = coord_bin(ci);
    int b = r_base[axis][u], n = r_hist[axis][u];
    int r = 0;
    for (int m = 0; m < n; m++) {
        int j = r_slot[axis][b + m];
        float cj = coords[j * 3 + axis];
        r += (int)((cj < ci) || (cj == ci && j < i));
    }
    g_rank[axis][i] = b + r;
}

// ------------------------- bucket keys (analytic bit width) + histogram -------------------------
__global__ void key_k(const float* __restrict__ regions) {
    int row = blockIdx.y;
    int nh = row >> 3, h = row & 7;
    float qe = 16384.0f / regions[nh * 16 + h];
    float qp = 16384.0f / regions[nh * 16 + 8 + h];
    int maxre = (int)floorf(16383.0f / qe) + 1;
    int nb = (int)ceilf(log2f((float)maxre + 1.0f));
    int i = blockIdx.x * 256 + threadIdx.x;
    int re = (int)floorf((float)g_rank[0][i] / qe) + 1;
    int rp = (int)floorf((float)g_rank[1][i] / qp) + 1;
    int key = (rp << nb) | re;
    b_keys[row][i] = key;
    atomicAdd(&b_hist[row][key], 1);
}

__global__ void bucket_place_k() {
    int row = blockIdx.y;
    int i = blockIdx.x * 256 + threadIdx.x;
    int key = b_keys[row][i];
    int slot = b_base[row][key] + atomicAdd(&b_cnt[row][key], 1);
    b_slot[row][slot] = i;
}

__global__ void bucket_pos_k() {
    int row = blockIdx.y;
    int i = blockIdx.x * 256 + threadIdx.x;
    int key = b_keys[row][i];
    int b = b_base[row][key], n = b_hist[row][key];
    int r = 0;
    for (int m = 0; m < n; m++) r += (int)(b_slot[row][b + m] < i);
    g_order[row * NNODE + b + r] = i;
}

// ------------------------- RPE distance weights (all 4 layers) -------------------------
__global__ void w2all_k(const float* __restrict__ wrpe) {   // [4][512][16]
    __shared__ float sq[128];
    int l = blockIdx.x;
    const float* w = wrpe + (size_t)l * 512 * 16;
    int t = threadIdx.x;
    int h = t >> 4, m = t & 15;
    float s = 0.f;
    for (int d = 0; d < 64; d++) s += w[(h * 64 + d) * 16 + m];
    float om = s * (1.0f / 64.0f);
    sq[t] = om * om;
    __syncthreads();
    if (t < 16) {
        int hh = t >> 1, c = t & 1;
        float ww = 0.f;
        for (int kk = 0; kk < 8; kk++) ww += sq[hh * 16 + c * 8 + kk];
        g_W2[l * 16 + t] = ww;
    }
}

// ------------------------- M_h[d][e] = sum_c Wq[d,c] Wk[e,c] / 8 (exact fp32, NT) -------------------------
#define FMA16(av, bv, acc)                                                         \
    acc[0][0]+=av.x*bv.x; acc[0][1]+=av.x*bv.y; acc[0][2]+=av.x*bv.z; acc[0][3]+=av.x*bv.w; \
    acc[1][0]+=av.y*bv.x; acc[1][1]+=av.y*bv.y; acc[1][2]+=av.y*bv.z; acc[1][3]+=av.y*bv.w; \
    acc[2][0]+=av.z*bv.x; acc[2][1]+=av.z*bv.y; acc[2][2]+=av.z*bv.z; acc[2][3]+=av.z*bv.w; \
    acc[3][0]+=av.w*bv.x; acc[3][1]+=av.w*bv.y; acc[3][2]+=av.w*bv.z; acc[3][3]+=av.w*bv.w;

__global__ void __launch_bounds__(256) mh_k(const float* __restrict__ wq,
                                            const float* __restrict__ wk) {
    __shared__ float Aq[64 * 68];   // [d][c]
    __shared__ float Bk[64 * 68];   // [e][c]
    int bx = blockIdx.x;            // l*8 + h
    int l = bx >> 3, h = bx & 7;
    int tid = threadIdx.x;
#pragma unroll
    for (int it = 0; it < 4; it++) {
        int idx = tid + it * 256;
        int d = idx >> 4, c4 = (idx & 15) * 4;
        *(float4*)&Aq[d * 68 + c4] = *(const float4*)&wq[((size_t)(l * 64 + d)) * 512 + h * 64 + c4];
        *(float4*)&Bk[d * 68 + c4] = *(const float4*)&wk[((size_t)(l * 64 + d)) * 512 + h * 64 + c4];
    }
    __syncthreads();
    int tm = tid >> 4, tn = tid & 15;
    float acc[4][4] = {};
#pragma unroll 4
    for (int c = 0; c < 64; c++) {
        float4 av = make_float4(Aq[(tm * 4 + 0) * 68 + c], Aq[(tm * 4 + 1) * 68 + c],
                                Aq[(tm * 4 + 2) * 68 + c], Aq[(tm * 4 + 3) * 68 + c]);
        float4 bv = make_float4(Bk[(tn * 4 + 0) * 68 + c], Bk[(tn * 4 + 1) * 68 + c],
                                Bk[(tn * 4 + 2) * 68 + c], Bk[(tn * 4 + 3) * 68 + c]);
        FMA16(av, bv, acc)
    }
#pragma unroll
    for (int ii = 0; ii < 4; ii++)
#pragma unroll
        for (int jj = 0; jj < 4; jj++)
            g_M[(size_t)bx * 4096 + (tm * 4 + ii) * 64 + tn * 4 + jj] = 0.125f * acc[ii][jj];
}

// ------------------------- G_h = Wv_h @ Ow_h (exact, NN); stored tf32-pre-rounded ------------------
__global__ void __launch_bounds__(256) gw_k(const float* __restrict__ wv,
                                            const float* __restrict__ ow) {
    __shared__ float Av[64 * 68];   // [d][c]
    __shared__ float Bo[64 * 68];   // [c][e]
    int bx = blockIdx.x;            // l*8 + h
    int l = bx >> 3, h = bx & 7;
    int tid = threadIdx.x;
#pragma unroll
    for (int it = 0; it < 4; it++) {
        int idx = tid + it * 256;
        int r = idx >> 4, c4 = (idx & 15) * 4;
        *(float4*)&Av[r * 68 + c4] = *(const float4*)&wv[((size_t)(l * 64 + r)) * 512 + h * 64 + c4];
        *(float4*)&Bo[r * 68 + c4] = *(const float4*)&ow[((size_t)(l * 512 + h * 64 + r)) * 64 + c4];
    }
    __syncthreads();
    int tm = tid >> 4, tn = tid & 15;
    float acc[4][4] = {};
#pragma unroll 4
    for (int c = 0; c < 64; c++) {
        float4 av = make_float4(Av[(tm * 4 + 0) * 68 + c], Av[(tm * 4 + 1) * 68 + c],
                                Av[(tm * 4 + 2) * 68 + c], Av[(tm * 4 + 3) * 68 + c]);
        float4 bv = *(const float4*)&Bo[c * 68 + tn * 4];
        FMA16(av, bv, acc)
    }
#pragma unroll
    for (int ii = 0; ii < 4; ii++)
#pragma unroll
        for (int jj = 0; jj < 4; jj++)
            g_G[(size_t)bx * 4096 + (tm * 4 + ii) * 64 + tn * 4 + jj] =
                __uint_as_float(f2tf(acc[ii][jj]));
}

// ------------------------- shared LN helper; writes tf32-pre-rounded output -------------------------
__device__ __forceinline__ void ln64_smem(const float* Xs, float (*redA)[4],
                                          const float* g, const float* b,
                                          float* dst, int row0, int tid) {
    int tr = tid >> 2, tp = tid & 3;
    float s = 0.f;
    for (int c = tp * 16; c < tp * 16 + 16; c++) s += Xs[tr * 68 + c];
    redA[tr][tp] = s;
    __syncthreads();
    float mu = (redA[tr][0] + redA[tr][1] + redA[tr][2] + redA[tr][3]) * (1.0f / 64.0f);
    __syncthreads();
    float vs = 0.f;
    for (int c = tp * 16; c < tp * 16 + 16; c++) {
        float d = Xs[tr * 68 + c] - mu;
        vs += d * d;
    }
    redA[tr][tp] = vs;
    __syncthreads();
    float var = (redA[tr][0] + redA[tr][1] + redA[tr][2] + redA[tr][3]) * (1.0f / 64.0f);
    float rs = rsqrtf(var + 1e-5f);
    for (int c = tp * 16; c < tp * 16 + 16; c++) {
        float vv = (Xs[tr * 68 + c] - mu) * rs * g[c] + b[c];
        dst[(size_t)(row0 + tr) * 64 + c] = __uint_as_float(f2tf(vv));
    }
}

// ------------------------- fused feat encoder + LN1(layer0) (exact FFMA) -------------------------
__global__ void __launch_bounds__(256) ffe_k(
    const float* __restrict__ x,
    const float* __restrict__ W1, const float* __restrict__ b1,
    const float* __restrict__ W2, const float* __restrict__ b2,
    const float* __restrict__ lng, const float* __restrict__ lnb)
{
    __shared__ float Xs16[64 * 17];
    __shared__ float W1s[16 * 68];
    __shared__ float Ts[64 * 68];
    __shared__ float W2s[64 * 68];
    __shared__ float redA[64][4];
    int tid = threadIdx.x;
    int row0 = blockIdx.x * 64;
    {
        int r = tid >> 2, c4 = (tid & 3) * 4;
        float4 xv = *(const float4*)&x[(size_t)(row0 + r) * 16 + c4];
        Xs16[r * 17 + c4 + 0] = xv.x; Xs16[r * 17 + c4 + 1] = xv.y;
        Xs16[r * 17 + c4 + 2] = xv.z; Xs16[r * 17 + c4 + 3] = xv.w;
    }
    if (tid < 16 * 16) {
        int r = tid >> 4, c4 = (tid & 15) * 4;
        *(float4*)&W1s[r * 68 + c4] = *(const float4*)&W1[(size_t)r * 64 + c4];
    }
#pragma unroll
    for (int it = 0; it < 4; it++) {
        int idx = tid + it * 256;
        int r = idx >> 4, c4 = (idx & 15) * 4;
        *(float4*)&W2s[r * 68 + c4] = *(const float4*)&W2[(size_t)r * 64 + c4];
    }
    __syncthreads();
    int tm = tid >> 4, tn = tid & 15;
    float acc[4][4] = {};
#pragma unroll
    for (int kk = 0; kk < 16; kk++) {
        float4 av = make_float4(Xs16[(tm * 4 + 0) * 17 + kk], Xs16[(tm * 4 + 1) * 17 + kk],
                                Xs16[(tm * 4 + 2) * 17 + kk], Xs16[(tm * 4 + 3) * 17 + kk]);
        float4 bv = *(const float4*)&W1s[kk * 68 + tn * 4];
        FMA16(av, bv, acc)
    }
#pragma unroll
    for (int ii = 0; ii < 4; ii++)
#pragma unroll
        for (int jj = 0; jj < 4; jj++)
            Ts[(tm * 4 + ii) * 68 + tn * 4 + jj] = fmaxf(acc[ii][jj] + b1[tn * 4 + jj], 0.f);
    __syncthreads();
    float acc2[4][4] = {};
#pragma unroll 8
    for (int kk = 0; kk < 64; kk++) {
        float4 av = make_float4(Ts[(tm * 4 + 0) * 68 + kk], Ts[(tm * 4 + 1) * 68 + kk],
                                Ts[(tm * 4 + 2) * 68 + kk], Ts[(tm * 4 + 3) * 68 + kk]);
        float4 bv = *(const float4*)&W2s[kk * 68 + tn * 4];
        FMA16(av, bv, acc2)
    }
    __syncthreads();
#pragma unroll
    for (int ii = 0; ii < 4; ii++) {
        int r = row0 + tm * 4 + ii;
#pragma unroll
        for (int jj = 0; jj < 4; jj++) {
            int c = tn * 4 + jj;
            float vv = acc2[ii][jj] + b2[c];
            g_h[(size_t)r * 64 + c] = vv;
            g_hist[(size_t)r * 320 + c] = vv;
            W2s[(tm * 4 + ii) * 68 + c] = vv;   // stage for LN
        }
    }
    __syncthreads();
    ln64_smem(W2s, redA, lng, lnb, (float*)g_xn, row0, tid);
}

// ------------------------- T = Xn @ M_h  (all nodes, per head), pre-rounded output -------------------------
__global__ void __launch_bounds__(256) tq_k(const float* __restrict__ Mbase) {
    __shared__ unsigned As[64 * 68];
    __shared__ unsigned Bs[64 * 68];
    int tid = threadIdx.x;
    int row0 = blockIdx.x * 64, h = blockIdx.y;
    const float* Mg = Mbase + (size_t)h * 4096;
#pragma unroll
    for (int it = 0; it < 4; it++) {
        int idx = tid + it * 256;
        int r = idx >> 4, c4 = (idx & 15) * 4;
        cp16(&As[r * 68 + c4], &g_xn[(size_t)(row0 + r) * 64 + c4]);   // pre-rounded
        float4 bv = *(const float4*)&Mg[r * 64 + c4];
        Bs[r * 68 + c4 + 0] = f2tf(bv.x); Bs[r * 68 + c4 + 1] = f2tf(bv.y);
        Bs[r * 68 + c4 + 2] = f2tf(bv.z); Bs[r * 68 + c4 + 3] = f2tf(bv.w);
    }
    asm volatile("cp.async.commit_group;");
    asm volatile("cp.async.wait_group 0;");
    __syncthreads();
    int wid = tid >> 5, lane = tid & 31;
    int g = lane >> 2, t = lane & 3;
    int r0 = (wid & 3) * 16, c0 = (wid >> 2) * 32;
    float acc[4][4] = {};
#pragma unroll
    for (int ks = 0; ks < 8; ks++) {
        int k0 = ks * 8;
        unsigned a0 = As[(r0 + g) * 68 + k0 + t];
        unsigned a1 = As[(r0 + g + 8) * 68 + k0 + t];
        unsigned a2 = As[(r0 + g) * 68 + k0 + t + 4];
        unsigned a3 = As[(r0 + g + 8) * 68 + k0 + t + 4];
#pragma unroll
        for (int nt = 0; nt < 4; nt++) {
            int n = c0 + nt * 8 + g;
            unsigned b0 = Bs[(k0 + t) * 68 + n];
            unsigned b1 = Bs[(k0 + t + 4) * 68 + n];
            mma_tf32(acc[nt], a0, a1, a2, a3, b0, b1);
        }
    }
#pragma unroll
    for (int nt = 0; nt < 4; nt++)
#pragma unroll
        for (int cr = 0; cr < 4; cr++) {
            int r = row0 + r0 + g + (cr >> 1) * 8;
            int c = c0 + nt * 8 + 2 * t + (cr & 1);
            g_T[(size_t)r * 512 + h * 64 + c] = __uint_as_float(f2tf(acc[nt][cr]));
        }
}

// ------------------------- attention: single bucket/block (R12 config) -------------------------
__global__ void __launch_bounds__(256) attn_k(
    const float* __restrict__ coords, const float* __restrict__ W2row)
{
    __shared__ unsigned Xs[64 * 68];   // X tf32
    __shared__ unsigned Ts[64 * 68];   // T tf32 -> S float / P tf32 [j][i]
    __shared__ int   nd[64];
    __shared__ float cx[64], cy[64], redm[4][64], reds[4][64];

    int tid = threadIdx.x;
    int blk = blockIdx.x, h = blockIdx.y, nh = blockIdx.z;
    int row = nh * 8 + h;
    const int* ord = g_order + row * NNODE + blk * 64;
    if (tid < 64) {
        int nn = ord[tid];
        nd[tid] = nn;
        cx[tid] = coords[nn * 3 + 0];
        cy[tid] = coords[nn * 3 + 1];
    }
    __syncthreads();

#pragma unroll
    for (int it = 0; it < 4; it++) {
        int idx = tid + it * 256;               // 0..1023
        int i = idx >> 4, q = (idx & 15) * 4;
        size_t nb = (size_t)nd[i];
        cp16(&Xs[i * 68 + q], &g_xn[nb * 64 + q]);
        cp16(&Ts[i * 68 + q], &g_T[nb * 512 + h * 64 + q]);
    }
    asm volatile("cp.async.commit_group;");
    asm volatile("cp.async.wait_group 0;");
    __syncthreads();

    int wid = tid >> 5, lane = tid & 31;
    int g = lane >> 2, t = lane & 3;
    int r0 = (wid & 3) * 16, c0 = (wid >> 2) * 32;

    // S = T @ X^T (+RPE) in registers
    float acc[4][4] = {};
#pragma unroll
    for (int ks = 0; ks < 8; ks++) {
        int k0 = ks * 8;
        unsigned a0 = Ts[(r0 + g) * 68 + k0 + t];
        unsigned a1 = Ts[(r0 + g + 8) * 68 + k0 + t];
        unsigned a2 = Ts[(r0 + g) * 68 + k0 + t + 4];
        unsigned a3 = Ts[(r0 + g + 8) * 68 + k0 + t + 4];
#pragma unroll
        for (int nt = 0; nt < 4; nt++) {
            int j = c0 + nt * 8 + g;
            unsigned b0 = Xs[j * 68 + k0 + t];
            unsigned b1 = Xs[j * 68 + k0 + t + 4];
            mma_tf32(acc[nt], a0, a1, a2, a3, b0, b1);
        }
    }
    float W0 = W2row[h * 2 + 0], W1 = W2row[h * 2 + 1];
    __syncthreads();   // all reads of Ts done; reuse as S

    float* Sf = (float*)Ts;
#pragma unroll
    for (int nt = 0; nt < 4; nt++) {
        int j0 = c0 + nt * 8 + 2 * t;
#pragma unroll
        for (int cr = 0; cr < 4; cr++) {
            int i = r0 + g + (cr >> 1) * 8;
            int j = j0 + (cr & 1);
            float dx = cx[i] - cx[j], dy = cy[i] - cy[j];
            Sf[j * 68 + i] = acc[nt][cr] - W0 * dx * dx - W1 * dy * dy;
        }
    }
    __syncthreads();

    int ci = tid & 63, seg = tid >> 6;
    float ml = -3.0e38f;
#pragma unroll
    for (int jj = 0; jj < 16; jj++) ml = fmaxf(ml, Sf[(seg * 16 + jj) * 68 + ci]);
    redm[seg][ci] = ml;
    __syncthreads();
    float mm = fmaxf(fmaxf(redm[0][ci], redm[1][ci]), fmaxf(redm[2][ci], redm[3][ci]));
    float ev[16];
    float sl = 0.f;
#pragma unroll
    for (int jj = 0; jj < 16; jj++) {
        float e = __expf(Sf[(seg * 16 + jj) * 68 + ci] - mm);
        ev[jj] = e;
        sl += e;
    }
    reds[seg][ci] = sl;
    __syncthreads();
    float ssum = reds[0][ci] + reds[1][ci] + reds[2][ci] + reds[3][ci];
    float inv = 1.0f / ssum;
    if (seg == 0) g_lser[row * NNODE + nd[ci]] = mm + __logf(ssum);
    unsigned* Ps = Ts;
#pragma unroll
    for (int jj = 0; jj < 16; jj++)
        Ps[(seg * 16 + jj) * 68 + ci] = f2tf(ev[jj] * inv);
    __syncthreads();

    // R = P @ X
    float racc[4][4] = {};
#pragma unroll
    for (int ks = 0; ks < 8; ks++) {
        int k0 = ks * 8;
        unsigned a0 = Ps[(k0 + t) * 68 + r0 + g];
        unsigned a1 = Ps[(k0 + t) * 68 + r0 + g + 8];
        unsigned a2 = Ps[(k0 + t + 4) * 68 + r0 + g];
        unsigned a3 = Ps[(k0 + t + 4) * 68 + r0 + g + 8];
#pragma unroll
        for (int nt = 0; nt < 4; nt++) {
            int n = c0 + nt * 8 + g;
            unsigned b0 = Xs[(k0 + t) * 68 + n];
            unsigned b1 = Xs[(k0 + t + 4) * 68 + n];
            mma_tf32(racc[nt], a0, a1, a2, a3, b0, b1);
        }
    }
#pragma unroll
    for (int nt = 0; nt < 4; nt++) {
        int d0 = c0 + nt * 8 + 2 * t;
        int iA = r0 + g, iB = r0 + g + 8;
        *(float2*)&g_outr[((size_t)row * NNODE + nd[iA]) * 64 + d0] =
            make_float2(racc[nt][0], racc[nt][1]);
        *(float2*)&g_outr[((size_t)row * NNODE + nd[iB]) * 64 + d0] =
            make_float2(racc[nt][2], racc[nt][3]);
    }
}

// ------------------------- fused epilogue: outproj + LN2 + FFN + resid + hist + LN1(next) ----------
// dynamic smem: AsU[64*68] u32 | BsU[64*68] u32 | Hs[64*68] f32  (52224 bytes)
__global__ void __launch_bounds__(256) epi_k(
    const float* __restrict__ gG, const float* __restrict__ ob,
    const float* __restrict__ lg2, const float* __restrict__ lb2,
    const float* __restrict__ W1, const float* __restrict__ b1,
    const float* __restrict__ W2, const float* __restrict__ b2,
    float* __restrict__ hist,
    const float* __restrict__ lnn_g, const float* __restrict__ lnn_b)
{
    extern __shared__ unsigned dyn[];
    unsigned* AsU = dyn;
    unsigned* BsU = dyn + 64 * 68;
    float*    Hs  = (float*)(dyn + 2 * 64 * 68);
    __shared__ float redA[64][4];
    __shared__ float w0s[64], w1s[64];
    float* As = (float*)AsU;
    float* Ws = (float*)BsU;
    int tid = threadIdx.x;
    int row0 = blockIdx.x * 64;
    int wid = tid >> 5, lane = tid & 31;
    int g = lane >> 2, t = lane & 3;
    int r0 = (wid & 3) * 16, c0 = (wid >> 2) * 32;

    // ---- stage 1: out-projection with fused lse-combine over 8 heads ----
    float acc[4][4] = {};
    for (int h = 0; h < 8; h++) {
        __syncthreads();
        // issue async load of this head's (pre-rounded tf32) G tile first
#pragma unroll
        for (int it = 0; it < 4; it++) {
            int idx = tid + it * 256;
            int r = idx >> 4, c4 = (idx & 15) * 4;
            cp16(&BsU[r * 68 + c4], &gG[(size_t)h * 4096 + r * 64 + c4]);
        }
        asm volatile("cp.async.commit_group;");
        if (tid < 64) {
            int node = row0 + tid;
            float l0 = g_lser[h * NNODE + node];
            float l1 = g_lser[(8 + h) * NNODE + node];
            float m = fmaxf(l0, l1);
            float e0 = __expf(l0 - m), e1 = __expf(l1 - m);
            float inv = 1.0f / (e0 + e1);
            w0s[tid] = e0 * inv;
            w1s[tid] = e1 * inv;
        }
        __syncthreads();
#pragma unroll
        for (int it = 0; it < 4; it++) {
            int idx = tid + it * 256;
            int r = idx >> 4, c4 = (idx & 15) * 4;
            int node = row0 + r;
            float4 o0 = *(const float4*)&g_outr[((size_t)h * NNODE + node) * 64 + c4];
            float4 o1 = *(const float4*)&g_outr[((size_t)(8 + h) * NNODE + node) * 64 + c4];
            float w0 = w0s[r], w1 = w1s[r];
            AsU[r * 68 + c4 + 0] = f2tf(w0 * o0.x + w1 * o1.x);
            AsU[r * 68 + c4 + 1] = f2tf(w0 * o0.y + w1 * o1.y);
            AsU[r * 68 + c4 + 2] = f2tf(w0 * o0.z + w1 * o1.z);
            AsU[r * 68 + c4 + 3] = f2tf(w0 * o0.w + w1 * o1.w);
        }
        asm volatile("cp.async.wait_group 0;");
        __syncthreads();
#pragma unroll
        for (int ks = 0; ks < 8; ks++) {
            int k0 = ks * 8;
            unsigned a0 = AsU[(r0 + g) * 68 + k0 + t];
            unsigned a1 = AsU[(r0 + g + 8) * 68 + k0 + t];
            unsigned a2 = AsU[(r0 + g) * 68 + k0 + t + 4];
            unsigned a3 = AsU[(r0 + g + 8) * 68 + k0 + t + 4];
#pragma unroll
            for (int nt = 0; nt < 4; nt++) {
                int n = c0 + nt * 8 + g;
                unsigned b0 = BsU[(k0 + t) * 68 + n];
                unsigned b1 = BsU[(k0 + t + 4) * 68 + n];
                mma_tf32(acc[nt], a0, a1, a2, a3, b0, b1);
            }
        }
    }
    __syncthreads();
#pragma unroll
    for (int nt = 0; nt < 4; nt++) {
#pragma unroll
        for (int cr = 0; cr < 4; cr++) {
            int rl = r0 + g + (cr >> 1) * 8;
            int ccol = c0 + nt * 8 + 2 * t + (cr & 1);
            Hs[rl * 68 + ccol] = acc[nt][cr] + ob[ccol] + g_h[(size_t)(row0 + rl) * 64 + ccol];
        }
    }
    __syncthreads();

    // ---- stage 2: LN2 (Hs -> As) + load W1 ----
    {
        int tr = tid >> 2, tp = tid & 3;
        float s = 0.f;
        for (int c = tp * 16; c < tp * 16 + 16; c++) s += Hs[tr * 68 + c];
        redA[tr][tp] = s;
        __syncthreads();
        float mu = (redA[tr][0] + redA[tr][1] + redA[tr][2] + redA[tr][3]) * (1.0f / 64.0f);
        __syncthreads();
        float vs = 0.f;
        for (int c = tp * 16; c < tp * 16 + 16; c++) {
            float d = Hs[tr * 68 + c] - mu;
            vs += d * d;
        }
        redA[tr][tp] = vs;
        __syncthreads();
        float var = (redA[tr][0] + redA[tr][1] + redA[tr][2] + redA[tr][3]) * (1.0f / 64.0f);
        float rs = rsqrtf(var + 1e-5f);
        for (int c = tp * 16; c < tp * 16 + 16; c++)
            As[tr * 68 + c] = (Hs[tr * 68 + c] - mu) * rs * lg2[c] + lb2[c];
    }
#pragma unroll
    for (int it = 0; it < 4; it++) {
        int idx = tid + it * 256;
        int r = idx >> 4, c4 = (idx & 15) * 4;
        *(float4*)&Ws[r * 68 + c4] = *(const float4*)&W1[(size_t)r * 64 + c4];
    }
    __syncthreads();

    // ---- stage 3: FFN ----
    int tm = tid >> 4, tn = tid & 15;
    float ac1[4][4] = {};
#pragma unroll 8
    for (int kk = 0; kk < 64; kk++) {
        float4 bv = *(const float4*)&Ws[kk * 68 + tn * 4];
        float4 av = make_float4(As[(tm * 4 + 0) * 68 + kk], As[(tm * 4 + 1) * 68 + kk],
                                As[(tm * 4 + 2) * 68 + kk], As[(tm * 4 + 3) * 68 + kk]);
        FMA16(av, bv, ac1)
    }
    __syncthreads();
#pragma unroll
    for (int ii = 0; ii < 4; ii++)
#pragma unroll
        for (int jj = 0; jj < 4; jj++)
            As[(tm * 4 + ii) * 68 + tn * 4 + jj] = fmaxf(ac1[ii][jj] + b1[tn * 4 + jj], 0.f);
#pragma unroll
    for (int it = 0; it < 4; it++) {
        int idx = tid + it * 256;
        int r = idx >> 4, c4 = (idx & 15) * 4;
        *(float4*)&Ws[r * 68 + c4] = *(const float4*)&W2[(size_t)r * 64 + c4];
    }
    __syncthreads();
    float ac2[4][4] = {};
#pragma unroll 8
    for (int kk = 0; kk < 64; kk++) {
        float4 bv = *(const float4*)&Ws[kk * 68 + tn * 4];
        float4 av = make_float4(As[(tm * 4 + 0) * 68 + kk], As[(tm * 4 + 1) * 68 + kk],
                                As[(tm * 4 + 2) * 68 + kk], As[(tm * 4 + 3) * 68 + kk]);
        FMA16(av, bv, ac2)
    }
    __syncthreads();
#pragma unroll
    for (int ii = 0; ii < 4; ii++) {
        int r = row0 + tm * 4 + ii;
        int rl = tm * 4 + ii;
#pragma unroll
        for (int jj = 0; jj < 4; jj++) {
            int c = tn * 4 + jj;
            float vv = ac2[ii][jj] + b2[c] + Hs[rl * 68 + c];
            g_h[(size_t)r * 64 + c] = vv;
            hist[(size_t)r * 320 + c] = vv;
            As[rl * 68 + c] = vv;
        }
    }
    if (lnn_g) {
        __syncthreads();
        ln64_smem(As, redA, lnn_g, lnn_b, (float*)g_xn, row0, tid);
    }
}

// ------------------------- scalar FFMA SGEMM (head) -------------------------
__global__ void __launch_bounds__(256) gemm_k(
    const float* __restrict__ A, const float* __restrict__ B, float* __restrict__ C,
    const float* __restrict__ bias, const float* __restrict__ resid,
    int M, int N, int K, int act)
{
    __shared__ float As[16][68];
    __shared__ float Bs[16][68];
    int tid = threadIdx.x;
    int row0 = blockIdx.x * 64, col0 = blockIdx.y * 64;
    int tm = tid >> 4, tn = tid & 15;
    int arow = tid >> 2, ac = tid & 3;
    int bk = tid >> 4, bn = tid & 15;
    float acc[4][4] = {};
    for (int k0 = 0; k0 < K; k0 += 16) {
        float4 a = *(const float4*)&A[(size_t)(row0 + arow) * K + k0 + ac * 4];
        As[ac * 4 + 0][arow] = a.x; As[ac * 4 + 1][arow] = a.y;
        As[ac * 4 + 2][arow] = a.z; As[ac * 4 + 3][arow] = a.w;
        int bcol = col0 + bn * 4;
        float4 bv = make_float4(0.f, 0.f, 0.f, 0.f);
        if (bcol < N) bv = *(const float4*)&B[(size_t)(k0 + bk) * N + bcol];
        *(float4*)&Bs[bk][bn * 4] = bv;
        __syncthreads();
#pragma unroll
        for (int kk = 0; kk < 16; kk++) {
            float4 av = *(const float4*)&As[kk][tm * 4];
            float4 bw = *(const float4*)&Bs[kk][tn * 4];
            FMA16(av, bw, acc)
        }
        __syncthreads();
    }
#pragma unroll
    for (int ii = 0; ii < 4; ii++) {
        int r = row0 + tm * 4 + ii;
#pragma unroll
        for (int jj = 0; jj < 4; jj++) {
            int ccol = col0 + tn * 4 + jj;
            if (ccol < N) {
                float vv = acc[ii][jj];
                if (bias) vv += bias[ccol];
                if (act == 1) vv = fmaxf(vv, 0.f);
                else if (act == 2) vv = tanhf(vv);
                if (resid) vv += resid[(size_t)r * N + ccol];
                C[(size_t)r * N + ccol] = vv;
            }
        }
    }
}

// ------------------------- LayerNorm 256 + tanh, warp per row -------------------------
__global__ void ln256w_k(const float* __restrict__ in, float* __restrict__ out,
                         const float* __restrict__ g, const float* __restrict__ b) {
    int w = threadIdx.x >> 5, lane = threadIdx.x & 31;
    int row = blockIdx.x * 8 + w;
    const float* xr = in + (size_t)row * 256;
    float x[8];
    float s = 0.f;
#pragma unroll
    for (int m = 0; m < 8; m++) { x[m] = xr[lane + 32 * m]; s += x[m]; }
    for (int o = 16; o; o >>= 1) s += __shfl_xor_sync(0xffffffffu, s, o);
    float mu = s * (1.0f / 256.0f);
    float vs = 0.f;
#pragma unroll
    for (int m = 0; m < 8; m++) { float d = x[m] - mu; vs += d * d; }
    for (int o = 16; o; o >>= 1) vs += __shfl_xor_sync(0xffffffffu, vs, o);
    float rs = rsqrtf(vs * (1.0f / 256.0f) + 1e-5f);
#pragma unroll
    for (int m = 0; m < 8; m++) {
        int c = lane + 32 * m;
        out[(size_t)row * 256 + c] = tanhf((x[m] - mu) * rs * g[c] + b[c]);
    }
}

// ------------------------- reductions + final projection -------------------------
__global__ void red1_k(const float* __restrict__ t) {
    __shared__ float sm[256];
    int blk = blockIdx.x, tid = threadIdx.x;
    int col = tid & 31, r0 = tid >> 5;
    float s = 0.f;
    for (int r = r0; r < 128; r += 8) s += t[(size_t)(blk * 128 + r) * 32 + col];
    sm[tid] = s;
    __syncthreads();
    for (int s2 = 4; s2; s2 >>= 1) {
        if (r0 < s2) sm[tid] += sm[tid + s2 * 32];
        __syncthreads();
    }
    if (r0 == 0) g_part[blk * 32 + col] = sm[col];
}

__global__ void red2_k(const float* __restrict__ pw, const float* __restrict__ pb,
                       float* __restrict__ out) {
    __shared__ float mean[32];
    int t = threadIdx.x;
    if (t < 32) {
        float s = 0.f;
        for (int b = 0; b < 128; b++) s += g_part[b * 32 + t];
        mean[t] = s * (1.0f / 16384.0f);
    }
    __syncthreads();
    if (t < 32) {
        float s = pb[t];
        for (int c = 0; c < 32; c++) s += mean[c] * pw[c * 32 + t];
        out[t] = s;
    }
}

// ------------------------- host orchestration -------------------------
extern "C" void kernel_launch(void* const* d_in, const int* in_sizes, int n_in,
                              void* d_out, int out_size)
{
    const float* x      = (const float*)d_in[0];
    const float* coords = (const float*)d_in[1];
    const float* regions= (const float*)d_in[3];
    const float* fe_w1  = (const float*)d_in[4];
    const float* fe_b1  = (const float*)d_in[5];
    const float* fe_w2  = (const float*)d_in[6];
    const float* fe_b2  = (const float*)d_in[7];
    const float* ln1_g  = (const float*)d_in[8];
    const float* ln1_b  = (const float*)d_in[9];
    const float* wq     = (const float*)d_in[10];
    const float* wk     = (const float*)d_in[11];
    const float* wv     = (const float*)d_in[12];
    const float* wrpe   = (const float*)d_in[13];
    const float* ow     = (const float*)d_in[14];
    const float* ob     = (const float*)d_in[15];
    const float* ln2_g  = (const float*)d_in[16];
    const float* ln2_b  = (const float*)d_in[17];
    const float* f1w    = (const float*)d_in[18];
    const float* f1b    = (const float*)d_in[19];
    const float* f2w    = (const float*)d_in[20];
    const float* f2b    = (const float*)d_in[21];
    const float* Wcat   = (const float*)d_in[22];
    const float* m1w    = (const float*)d_in[23];
    const float* m1b    = (const float*)d_in[24];
    const float* mlng   = (const float*)d_in[25];
    const float* mlnb   = (const float*)d_in[26];
    const float* m2w    = (const float*)d_in[27];
    const float* m2b    = (const float*)d_in[28];
    const float* pw     = (const float*)d_in[29];
    const float* pb     = (const float*)d_in[30];
    float* out = (float*)d_out;

    cudaFuncSetAttribute(epi_k, cudaFuncAttributeMaxDynamicSharedMemorySize, 52224);

    float *p_hist, *p_t0, *p_u, *p_u2, *p_t, *p_w2, *p_M, *p_G;
    int *p_rhist, *p_rbase, *p_bhist, *p_bbase;
    cudaGetSymbolAddress((void**)&p_hist, g_hist);
    cudaGetSymbolAddress((void**)&p_t0,   g_t0);
    cudaGetSymbolAddress((void**)&p_u,    g_u);
    cudaGetSymbolAddress((void**)&p_u2,   g_u2);
    cudaGetSymbolAddress((void**)&p_t,    g_t);
    cudaGetSymbolAddress((void**)&p_w2,   g_W2);
    cudaGetSymbolAddress((void**)&p_M,    g_M);
    cudaGetSymbolAddress((void**)&p_G,    g_G);
    cudaGetSymbolAddress((void**)&p_rhist, r_hist);
    cudaGetSymbolAddress((void**)&p_rbase, r_base);
    cudaGetSymbolAddress((void**)&p_bhist, b_hist);
    cudaGetSymbolAddress((void**)&p_bbase, b_base);

    const int M = NNODE;

    // ---- bucket ordering via counting sorts (R12 config) ----
    zero_k<<<512, 256>>>();
    rank_hist_k<<<dim3(64, 2), 256>>>(coords);
    scan_k<<<2, 1024>>>(p_rhist, p_rbase, NNODE, NNODE);
    rank_place_k<<<dim3(64, 2), 256>>>(coords);
    rank_rank_k<<<dim3(64, 2), 256>>>(coords);
    key_k<<<dim3(64, 16), 256>>>(regions);
    scan_k<<<16, 1024>>>(p_bhist, p_bbase, KBINS, KBINS);
    bucket_place_k<<<dim3(64, 16), 256>>>();
    bucket_pos_k<<<dim3(64, 16), 256>>>();
    w2all_k<<<4, 128>>>(wrpe);
    mh_k<<<32, 256>>>(wq, wk);
    gw_k<<<32, 256>>>(wv, ow);

    // feat encoder + LN1(layer 0)
    ffe_k<<<256, 256>>>(x, fe_w1, fe_b1, fe_w2, fe_b2, ln1_g, ln1_b);

    for (int l = 0; l < 4; l++) {
        tq_k<<<dim3(256, 8), 256>>>(p_M + (size_t)l * 8 * 4096);
        attn_k<<<dim3(256, 8, 2), 256>>>(coords, p_w2 + l * 16);
        const float* nlg = (l < 3) ? (ln1_g + (l + 1) * 64) : nullptr;
        const float* nlb = (l < 3) ? (ln1_b + (l + 1) * 64) : nullptr;
        epi_k<<<256, 256, 52224>>>(p_G + (size_t)l * 8 * 4096, ob + l * 64,
                                   ln2_g + l * 64, ln2_b + l * 64,
                                   f1w + (size_t)l * 64 * 64, f1b + l * 64,
                                   f2w + (size_t)l * 64 * 64, f2b + l * 64,
                                   p_hist + (l + 1) * 64, nlg, nlb);
    }

    gemm_k<<<dim3(256, 1), 256>>>(p_hist, Wcat, p_t0, nullptr, nullptr, M, 32, 320, 2);
    gemm_k<<<dim3(256, 4), 256>>>(p_t0, m1w, p_u, m1b, nullptr, M, 256, 32, 0);
    ln256w_k<<<2048, 256>>>(p_u, p_u2, mlng, mlnb);
    gemm_k<<<dim3(256, 1), 256>>>(p_u2, m2w, p_t, m2b, p_t0, M, 32, 256, 0);
    red1_k<<<128, 256>>>(p_t);
    red2_k<<<1, 256>>>(pw, pb, out);
}

// round 17
// speedup vs baseline: 1.1515x; 1.0243x over previous
#include <cuda_runtime.h>
#include <cuda_bf16.h>
#include <math.h>

#define NNODE 16384
#define HEADS 8
#define DIM   64
#define HDIM  512
#define KBINS 40960

// ------------------------- device scratch (no allocs allowed) -------------------------
__device__ int   g_rank[2][NNODE];
__device__ int   g_order[16 * NNODE];
__device__ float g_h[NNODE * DIM];
__device__ float g_xn[NNODE * DIM];          // LN1(h), tf32-pre-rounded
__device__ float g_T[NNODE * HDIM];          // T = Xn @ M_h, tf32-pre-rounded
__device__ float g_hist[NNODE * 320];
__device__ float g_outr[16 * NNODE * DIM];   // R = P@X  [nh*8+h][node][d]
__device__ float g_lser[16 * NNODE];
__device__ float g_W2[4 * 16];               // [layer][h][c]
__device__ float g_M[4 * 8 * 64 * 64];       // [layer][head][d][e] = sum_c Wq[d,c]Wk[e,c]/8
__device__ float g_G[4 * 8 * 64 * 64];       // [layer][head][d][e] = Wv_h @ Ow_h (tf32-pre-rounded)
__device__ float g_t0[NNODE * 32];
__device__ float g_part0[256 * 32];
__device__ float g_part2[256 * 256];

// sorting scratch
__device__ int r_hist[2][NNODE];
__device__ int r_base[2][NNODE];
__device__ int r_cnt [2][NNODE];
__device__ int r_slot[2][NNODE];
__device__ int b_keys[16][NNODE];
__device__ int b_hist[16][KBINS];
__device__ int b_base[16][KBINS];
__device__ int b_cnt [16][KBINS];
__device__ int b_slot[16][NNODE];

// ------------------------- tf32 / async helpers -------------------------
__device__ __forceinline__ unsigned f2tf(float f) {
    unsigned u;
    asm("cvt.rna.tf32.f32 %0, %1;" : "=r"(u) : "f"(f));
    return u;
}

__device__ __forceinline__ void mma_tf32(float c[4], unsigned a0, unsigned a1,
                                         unsigned a2, unsigned a3,
                                         unsigned b0, unsigned b1) {
    asm volatile(
        "mma.sync.aligned.m16n8k8.row.col.f32.tf32.tf32.f32 "
        "{%0,%1,%2,%3}, {%4,%5,%6,%7}, {%8,%9}, {%0,%1,%2,%3};"
        : "+f"(c[0]), "+f"(c[1]), "+f"(c[2]), "+f"(c[3])
        : "r"(a0), "r"(a1), "r"(a2), "r"(a3), "r"(b0), "r"(b1));
}

__device__ __forceinline__ void cp16(void* smem, const void* gmem) {
    unsigned sa = (unsigned)__cvta_generic_to_shared(smem);
    asm volatile("cp.async.cg.shared.global [%0], [%1], 16;" :: "r"(sa), "l"(gmem));
}

// ------------------------- zero all counting scratch -------------------------
__global__ void zero_k() {
    int gid = blockIdx.x * 256 + threadIdx.x;
    int stride = gridDim.x * 256;
    for (int i = gid; i < 2 * NNODE; i += stride) { ((int*)r_hist)[i] = 0; ((int*)r_cnt)[i] = 0; }
    for (int i = gid; i < 16 * KBINS; i += stride) { ((int*)b_hist)[i] = 0; ((int*)b_cnt)[i] = 0; }
}

// ------------------------- coordinate ranks via counting -------------------------
__device__ __forceinline__ int coord_bin(float c) {
    int u = (int)(c * 16384.0f);
    return min(16383, max(0, u));
}

__global__ void rank_hist_k(const float* __restrict__ coords) {
    int axis = blockIdx.y;
    int i = blockIdx.x * 256 + threadIdx.x;
    int u = coord_bin(coords[i * 3 + axis]);
    atomicAdd(&r_hist[axis][u], 1);
}

__global__ void __launch_bounds__(1024) scan_k(const int* __restrict__ hist,
                                               int* __restrict__ base,
                                               int nbins, int rowstride) {
    __shared__ int ss[1024];
    int row = blockIdx.x;
    const int* h = hist + (size_t)row * rowstride;
    int* bs = base + (size_t)row * rowstride;
    int t = threadIdx.x;
    int chunk = (nbins + 1023) >> 10;
    int b0 = t * chunk;
    int s = 0;
    for (int m = 0; m < chunk; m++) { int idx = b0 + m; if (idx < nbins) s += h[idx]; }
    ss[t] = s;
    __syncthreads();
    for (int d = 1; d < 1024; d <<= 1) {
        int v = (t >= d) ? ss[t - d] : 0;
        __syncthreads();
        ss[t] += v;
        __syncthreads();
    }
    int run = (t > 0) ? ss[t - 1] : 0;
    for (int m = 0; m < chunk; m++) {
        int idx = b0 + m;
        if (idx < nbins) { bs[idx] = run; run += h[idx]; }
    }
}

__global__ void rank_place_k(const float* __restrict__ coords) {
    int axis = blockIdx.y;
    int i = blockIdx.x * 256 + threadIdx.x;
    int u = coord_bin(coords[i * 3 + axis]);
    int slot = r_base[axis][u] + atomicAdd(&r_cnt[axis][u], 1);
    r_slot[axis][slot] = i;
}

__global__ void rank_rank_k(const float* __restrict__ coords) {
    int axis = blockIdx.y;
    int i = blockIdx.x * 256 + threadIdx.x;
    float ci = coords[i * 3 + axis];
    int u = coord_bin(ci);
    int b = r_base[axis][u], n = r_hist[axis][u];
    int r = 0;
    for (int m = 0; m < n; m++) {
        int j = r_slot[axis][b + m];
        float cj = coords[j * 3 + axis];
        r += (int)((cj < ci) || (cj == ci && j < i));
    }
    g_rank[axis][i] = b + r;
}

// ------------------------- bucket keys (analytic bit width) + histogram -------------------------
__global__ void key_k(const float* __restrict__ regions) {
    int row = blockIdx.y;
    int nh = row >> 3, h = row & 7;
    float qe = 16384.0f / regions[nh * 16 + h];
    float qp = 16384.0f / regions[nh * 16 + 8 + h];
    int maxre = (int)floorf(16383.0f / qe) + 1;
    int nb = (int)ceilf(log2f((float)maxre + 1.0f));
    int i = blockIdx.x * 256 + threadIdx.x;
    int re = (int)floorf((float)g_rank[0][i] / qe) + 1;
    int rp = (int)floorf((float)g_rank[1][i] / qp) + 1;
    int key = (rp << nb) | re;
    b_keys[row][i] = key;
    atomicAdd(&b_hist[row][key], 1);
}

__global__ void bucket_place_k() {
    int row = blockIdx.y;
    int i = blockIdx.x * 256 + threadIdx.x;
    int key = b_keys[row][i];
    int slot = b_base[row][key] + atomicAdd(&b_cnt[row][key], 1);
    b_slot[row][slot] = i;
}

__global__ void bucket_pos_k() {
    int row = blockIdx.y;
    int i = blockIdx.x * 256 + threadIdx.x;
    int key = b_keys[row][i];
    int b = b_base[row][key], n = b_hist[row][key];
    int r = 0;
    for (int m = 0; m < n; m++) r += (int)(b_slot[row][b + m] < i);
    g_order[row * NNODE + b + r] = i;
}

// ------------------------- RPE distance weights (all 4 layers) -------------------------
__global__ void w2all_k(const float* __restrict__ wrpe) {   // [4][512][16]
    __shared__ float sq[128];
    int l = blockIdx.x;
    const float* w = wrpe + (size_t)l * 512 * 16;
    int t = threadIdx.x;
    int h = t >> 4, m = t & 15;
    float s = 0.f;
    for (int d = 0; d < 64; d++) s += w[(h * 64 + d) * 16 + m];
    float om = s * (1.0f / 64.0f);
    sq[t] = om * om;
    __syncthreads();
    if (t < 16) {
        int hh = t >> 1, c = t & 1;
        float ww = 0.f;
        for (int kk = 0; kk < 8; kk++) ww += sq[hh * 16 + c * 8 + kk];
        g_W2[l * 16 + t] = ww;
    }
}

// ------------------------- M_h[d][e] = sum_c Wq[d,c] Wk[e,c] / 8 (exact fp32, NT) -------------------------
#define FMA16(av, bv, acc)                                                         \
    acc[0][0]+=av.x*bv.x; acc[0][1]+=av.x*bv.y; acc[0][2]+=av.x*bv.z; acc[0][3]+=av.x*bv.w; \
    acc[1][0]+=av.y*bv.x; acc[1][1]+=av.y*bv.y; acc[1][2]+=av.y*bv.z; acc[1][3]+=av.y*bv.w; \
    acc[2][0]+=av.z*bv.x; acc[2][1]+=av.z*bv.y; acc[2][2]+=av.z*bv.z; acc[2][3]+=av.z*bv.w; \
    acc[3][0]+=av.w*bv.x; acc[3][1]+=av.w*bv.y; acc[3][2]+=av.w*bv.z; acc[3][3]+=av.w*bv.w;

__global__ void __launch_bounds__(256) mh_k(const float* __restrict__ wq,
                                            const float* __restrict__ wk) {
    __shared__ float Aq[64 * 68];   // [d][c]
    __shared__ float Bk[64 * 68];   // [e][c]
    int bx = blockIdx.x;            // l*8 + h
    int l = bx >> 3, h = bx & 7;
    int tid = threadIdx.x;
#pragma unroll
    for (int it = 0; it < 4; it++) {
        int idx = tid + it * 256;
        int d = idx >> 4, c4 = (idx & 15) * 4;
        *(float4*)&Aq[d * 68 + c4] = *(const float4*)&wq[((size_t)(l * 64 + d)) * 512 + h * 64 + c4];
        *(float4*)&Bk[d * 68 + c4] = *(const float4*)&wk[((size_t)(l * 64 + d)) * 512 + h * 64 + c4];
    }
    __syncthreads();
    int tm = tid >> 4, tn = tid & 15;
    float acc[4][4] = {};
#pragma unroll 4
    for (int c = 0; c < 64; c++) {
        float4 av = make_float4(Aq[(tm * 4 + 0) * 68 + c], Aq[(tm * 4 + 1) * 68 + c],
                                Aq[(tm * 4 + 2) * 68 + c], Aq[(tm * 4 + 3) * 68 + c]);
        float4 bv = make_float4(Bk[(tn * 4 + 0) * 68 + c], Bk[(tn * 4 + 1) * 68 + c],
                                Bk[(tn * 4 + 2) * 68 + c], Bk[(tn * 4 + 3) * 68 + c]);
        FMA16(av, bv, acc)
    }
#pragma unroll
    for (int ii = 0; ii < 4; ii++)
#pragma unroll
        for (int jj = 0; jj < 4; jj++)
            g_M[(size_t)bx * 4096 + (tm * 4 + ii) * 64 + tn * 4 + jj] = 0.125f * acc[ii][jj];
}

// ------------------------- G_h = Wv_h @ Ow_h (exact, NN); stored tf32-pre-rounded ------------------
__global__ void __launch_bounds__(256) gw_k(const float* __restrict__ wv,
                                            const float* __restrict__ ow) {
    __shared__ float Av[64 * 68];   // [d][c]
    __shared__ float Bo[64 * 68];   // [c][e]
    int bx = blockIdx.x;            // l*8 + h
    int l = bx >> 3, h = bx & 7;
    int tid = threadIdx.x;
#pragma unroll
    for (int it = 0; it < 4; it++) {
        int idx = tid + it * 256;
        int r = idx >> 4, c4 = (idx & 15) * 4;
        *(float4*)&Av[r * 68 + c4] = *(const float4*)&wv[((size_t)(l * 64 + r)) * 512 + h * 64 + c4];
        *(float4*)&Bo[r * 68 + c4] = *(const float4*)&ow[((size_t)(l * 512 + h * 64 + r)) * 64 + c4];
    }
    __syncthreads();
    int tm = tid >> 4, tn = tid & 15;
    float acc[4][4] = {};
#pragma unroll 4
    for (int c = 0; c < 64; c++) {
        float4 av = make_float4(Av[(tm * 4 + 0) * 68 + c], Av[(tm * 4 + 1) * 68 + c],
                                Av[(tm * 4 + 2) * 68 + c], Av[(tm * 4 + 3) * 68 + c]);
        float4 bv = *(const float4*)&Bo[c * 68 + tn * 4];
        FMA16(av, bv, acc)
    }
#pragma unroll
    for (int ii = 0; ii < 4; ii++)
#pragma unroll
        for (int jj = 0; jj < 4; jj++)
            g_G[(size_t)bx * 4096 + (tm * 4 + ii) * 64 + tn * 4 + jj] =
                __uint_as_float(f2tf(acc[ii][jj]));
}

// ------------------------- shared LN helper; writes tf32-pre-rounded output -------------------------
__device__ __forceinline__ void ln64_smem(const float* Xs, float (*redA)[4],
                                          const float* g, const float* b,
                                          float* dst, int row0, int tid) {
    int tr = tid >> 2, tp = tid & 3;
    float s = 0.f;
    for (int c = tp * 16; c < tp * 16 + 16; c++) s += Xs[tr * 68 + c];
    redA[tr][tp] = s;
    __syncthreads();
    float mu = (redA[tr][0] + redA[tr][1] + redA[tr][2] + redA[tr][3]) * (1.0f / 64.0f);
    __syncthreads();
    float vs = 0.f;
    for (int c = tp * 16; c < tp * 16 + 16; c++) {
        float d = Xs[tr * 68 + c] - mu;
        vs += d * d;
    }
    redA[tr][tp] = vs;
    __syncthreads();
    float var = (redA[tr][0] + redA[tr][1] + redA[tr][2] + redA[tr][3]) * (1.0f / 64.0f);
    float rs = rsqrtf(var + 1e-5f);
    for (int c = tp * 16; c < tp * 16 + 16; c++) {
        float vv = (Xs[tr * 68 + c] - mu) * rs * g[c] + b[c];
        dst[(size_t)(row0 + tr) * 64 + c] = __uint_as_float(f2tf(vv));
    }
}

// ------------------------- fused feat encoder + LN1(layer0) (exact FFMA) -------------------------
__global__ void __launch_bounds__(256) ffe_k(
    const float* __restrict__ x,
    const float* __restrict__ W1, const float* __restrict__ b1,
    const float* __restrict__ W2, const float* __restrict__ b2,
    const float* __restrict__ lng, const float* __restrict__ lnb)
{
    __shared__ float Xs16[64 * 17];
    __shared__ float W1s[16 * 68];
    __shared__ float Ts[64 * 68];
    __shared__ float W2s[64 * 68];
    __shared__ float redA[64][4];
    int tid = threadIdx.x;
    int row0 = blockIdx.x * 64;
    {
        int r = tid >> 2, c4 = (tid & 3) * 4;
        float4 xv = *(const float4*)&x[(size_t)(row0 + r) * 16 + c4];
        Xs16[r * 17 + c4 + 0] = xv.x; Xs16[r * 17 + c4 + 1] = xv.y;
        Xs16[r * 17 + c4 + 2] = xv.z; Xs16[r * 17 + c4 + 3] = xv.w;
    }
    if (tid < 16 * 16) {
        int r = tid >> 4, c4 = (tid & 15) * 4;
        *(float4*)&W1s[r * 68 + c4] = *(const float4*)&W1[(size_t)r * 64 + c4];
    }
#pragma unroll
    for (int it = 0; it < 4; it++) {
        int idx = tid + it * 256;
        int r = idx >> 4, c4 = (idx & 15) * 4;
        *(float4*)&W2s[r * 68 + c4] = *(const float4*)&W2[(size_t)r * 64 + c4];
    }
    __syncthreads();
    int tm = tid >> 4, tn = tid & 15;
    float acc[4][4] = {};
#pragma unroll
    for (int kk = 0; kk < 16; kk++) {
        float4 av = make_float4(Xs16[(tm * 4 + 0) * 17 + kk], Xs16[(tm * 4 + 1) * 17 + kk],
                                Xs16[(tm * 4 + 2) * 17 + kk], Xs16[(tm * 4 + 3) * 17 + kk]);
        float4 bv = *(const float4*)&W1s[kk * 68 + tn * 4];
        FMA16(av, bv, acc)
    }
#pragma unroll
    for (int ii = 0; ii < 4; ii++)
#pragma unroll
        for (int jj = 0; jj < 4; jj++)
            Ts[(tm * 4 + ii) * 68 + tn * 4 + jj] = fmaxf(acc[ii][jj] + b1[tn * 4 + jj], 0.f);
    __syncthreads();
    float acc2[4][4] = {};
#pragma unroll 8
    for (int kk = 0; kk < 64; kk++) {
        float4 av = make_float4(Ts[(tm * 4 + 0) * 68 + kk], Ts[(tm * 4 + 1) * 68 + kk],
                                Ts[(tm * 4 + 2) * 68 + kk], Ts[(tm * 4 + 3) * 68 + kk]);
        float4 bv = *(const float4*)&W2s[kk * 68 + tn * 4];
        FMA16(av, bv, acc2)
    }
    __syncthreads();
#pragma unroll
    for (int ii = 0; ii < 4; ii++) {
        int r = row0 + tm * 4 + ii;
#pragma unroll
        for (int jj = 0; jj < 4; jj++) {
            int c = tn * 4 + jj;
            float vv = acc2[ii][jj] + b2[c];
            g_h[(size_t)r * 64 + c] = vv;
            g_hist[(size_t)r * 320 + c] = vv;
            W2s[(tm * 4 + ii) * 68 + c] = vv;   // stage for LN
        }
    }
    __syncthreads();
    ln64_smem(W2s, redA, lng, lnb, (float*)g_xn, row0, tid);
}

// ------------------------- T = Xn @ M_h  (all nodes, per head), pre-rounded output -------------------------
__global__ void __launch_bounds__(256) tq_k(const float* __restrict__ Mbase) {
    __shared__ unsigned As[64 * 68];
    __shared__ unsigned Bs[64 * 68];
    int tid = threadIdx.x;
    int row0 = blockIdx.x * 64, h = blockIdx.y;
    const float* Mg = Mbase + (size_t)h * 4096;
#pragma unroll
    for (int it = 0; it < 4; it++) {
        int idx = tid + it * 256;
        int r = idx >> 4, c4 = (idx & 15) * 4;
        cp16(&As[r * 68 + c4], &g_xn[(size_t)(row0 + r) * 64 + c4]);   // pre-rounded
        float4 bv = *(const float4*)&Mg[r * 64 + c4];
        Bs[r * 68 + c4 + 0] = f2tf(bv.x); Bs[r * 68 + c4 + 1] = f2tf(bv.y);
        Bs[r * 68 + c4 + 2] = f2tf(bv.z); Bs[r * 68 + c4 + 3] = f2tf(bv.w);
    }
    asm volatile("cp.async.commit_group;");
    asm volatile("cp.async.wait_group 0;");
    __syncthreads();
    int wid = tid >> 5, lane = tid & 31;
    int g = lane >> 2, t = lane & 3;
    int r0 = (wid & 3) * 16, c0 = (wid >> 2) * 32;
    float acc[4][4] = {};
#pragma unroll
    for (int ks = 0; ks < 8; ks++) {
        int k0 = ks * 8;
        unsigned a0 = As[(r0 + g) * 68 + k0 + t];
        unsigned a1 = As[(r0 + g + 8) * 68 + k0 + t];
        unsigned a2 = As[(r0 + g) * 68 + k0 + t + 4];
        unsigned a3 = As[(r0 + g + 8) * 68 + k0 + t + 4];
#pragma unroll
        for (int nt = 0; nt < 4; nt++) {
            int n = c0 + nt * 8 + g;
            unsigned b0 = Bs[(k0 + t) * 68 + n];
            unsigned b1 = Bs[(k0 + t + 4) * 68 + n];
            mma_tf32(acc[nt], a0, a1, a2, a3, b0, b1);
        }
    }
#pragma unroll
    for (int nt = 0; nt < 4; nt++)
#pragma unroll
        for (int cr = 0; cr < 4; cr++) {
            int r = row0 + r0 + g + (cr >> 1) * 8;
            int c = c0 + nt * 8 + 2 * t + (cr & 1);
            g_T[(size_t)r * 512 + h * 64 + c] = __uint_as_float(f2tf(acc[nt][cr]));
        }
}

// ------------------------- attention: single bucket/block (R12 config) -------------------------
__global__ void __launch_bounds__(256) attn_k(
    const float* __restrict__ coords, const float* __restrict__ W2row)
{
    __shared__ unsigned Xs[64 * 68];   // X tf32
    __shared__ unsigned Ts[64 * 68];   // T tf32 -> S float / P tf32 [j][i]
    __shared__ int   nd[64];
    __shared__ float cx[64], cy[64], redm[4][64], reds[4][64];

    int tid = threadIdx.x;
    int blk = blockIdx.x, h = blockIdx.y, nh = blockIdx.z;
    int row = nh * 8 + h;
    const int* ord = g_order + row * NNODE + blk * 64;
    if (tid < 64) {
        int nn = ord[tid];
        nd[tid] = nn;
        cx[tid] = coords[nn * 3 + 0];
        cy[tid] = coords[nn * 3 + 1];
    }
    __syncthreads();

#pragma unroll
    for (int it = 0; it < 4; it++) {
        int idx = tid + it * 256;               // 0..1023
        int i = idx >> 4, q = (idx & 15) * 4;
        size_t nb = (size_t)nd[i];
        cp16(&Xs[i * 68 + q], &g_xn[nb * 64 + q]);
        cp16(&Ts[i * 68 + q], &g_T[nb * 512 + h * 64 + q]);
    }
    asm volatile("cp.async.commit_group;");
    asm volatile("cp.async.wait_group 0;");
    __syncthreads();

    int wid = tid >> 5, lane = tid & 31;
    int g = lane >> 2, t = lane & 3;
    int r0 = (wid & 3) * 16, c0 = (wid >> 2) * 32;

    // S = T @ X^T (+RPE) in registers
    float acc[4][4] = {};
#pragma unroll
    for (int ks = 0; ks < 8; ks++) {
        int k0 = ks * 8;
        unsigned a0 = Ts[(r0 + g) * 68 + k0 + t];
        unsigned a1 = Ts[(r0 + g + 8) * 68 + k0 + t];
        unsigned a2 = Ts[(r0 + g) * 68 + k0 + t + 4];
        unsigned a3 = Ts[(r0 + g + 8) * 68 + k0 + t + 4];
#pragma unroll
        for (int nt = 0; nt < 4; nt++) {
            int j = c0 + nt * 8 + g;
            unsigned b0 = Xs[j * 68 + k0 + t];
            unsigned b1 = Xs[j * 68 + k0 + t + 4];
            mma_tf32(acc[nt], a0, a1, a2, a3, b0, b1);
        }
    }
    float W0 = W2row[h * 2 + 0], W1 = W2row[h * 2 + 1];
    __syncthreads();   // all reads of Ts done; reuse as S

    float* Sf = (float*)Ts;
#pragma unroll
    for (int nt = 0; nt < 4; nt++) {
        int j0 = c0 + nt * 8 + 2 * t;
#pragma unroll
        for (int cr = 0; cr < 4; cr++) {
            int i = r0 + g + (cr >> 1) * 8;
            int j = j0 + (cr & 1);
            float dx = cx[i] - cx[j], dy = cy[i] - cy[j];
            Sf[j * 68 + i] = acc[nt][cr] - W0 * dx * dx - W1 * dy * dy;
        }
    }
    __syncthreads();

    int ci = tid & 63, seg = tid >> 6;
    float ml = -3.0e38f;
#pragma unroll
    for (int jj = 0; jj < 16; jj++) ml = fmaxf(ml, Sf[(seg * 16 + jj) * 68 + ci]);
    redm[seg][ci] = ml;
    __syncthreads();
    float mm = fmaxf(fmaxf(redm[0][ci], redm[1][ci]), fmaxf(redm[2][ci], redm[3][ci]));
    float ev[16];
    float sl = 0.f;
#pragma unroll
    for (int jj = 0; jj < 16; jj++) {
        float e = __expf(Sf[(seg * 16 + jj) * 68 + ci] - mm);
        ev[jj] = e;
        sl += e;
    }
    reds[seg][ci] = sl;
    __syncthreads();
    float ssum = reds[0][ci] + reds[1][ci] + reds[2][ci] + reds[3][ci];
    float inv = 1.0f / ssum;
    if (seg == 0) g_lser[row * NNODE + nd[ci]] = mm + __logf(ssum);
    unsigned* Ps = Ts;
#pragma unroll
    for (int jj = 0; jj < 16; jj++)
        Ps[(seg * 16 + jj) * 68 + ci] = f2tf(ev[jj] * inv);
    __syncthreads();

    // R = P @ X
    float racc[4][4] = {};
#pragma unroll
    for (int ks = 0; ks < 8; ks++) {
        int k0 = ks * 8;
        unsigned a0 = Ps[(k0 + t) * 68 + r0 + g];
        unsigned a1 = Ps[(k0 + t) * 68 + r0 + g + 8];
        unsigned a2 = Ps[(k0 + t + 4) * 68 + r0 + g];
        unsigned a3 = Ps[(k0 + t + 4) * 68 + r0 + g + 8];
#pragma unroll
        for (int nt = 0; nt < 4; nt++) {
            int n = c0 + nt * 8 + g;
            unsigned b0 = Xs[(k0 + t) * 68 + n];
            unsigned b1 = Xs[(k0 + t + 4) * 68 + n];
            mma_tf32(racc[nt], a0, a1, a2, a3, b0, b1);
        }
    }
#pragma unroll
    for (int nt = 0; nt < 4; nt++) {
        int d0 = c0 + nt * 8 + 2 * t;
        int iA = r0 + g, iB = r0 + g + 8;
        *(float2*)&g_outr[((size_t)row * NNODE + nd[iA]) * 64 + d0] =
            make_float2(racc[nt][0], racc[nt][1]);
        *(float2*)&g_outr[((size_t)row * NNODE + nd[iB]) * 64 + d0] =
            make_float2(racc[nt][2], racc[nt][3]);
    }
}

// ------------------------- fused epilogue: outproj + LN2 + FFN + resid + hist + LN1(next) ----------
// dynamic smem: AsU[64*68] u32 | BsU[64*68] u32 | Hs[64*68] f32  (52224 bytes)
__global__ void __launch_bounds__(256) epi_k(
    const float* __restrict__ gG, const float* __restrict__ ob,
    const float* __restrict__ lg2, const float* __restrict__ lb2,
    const float* __restrict__ W1, const float* __restrict__ b1,
    const float* __restrict__ W2, const float* __restrict__ b2,
    float* __restrict__ hist,
    const float* __restrict__ lnn_g, const float* __restrict__ lnn_b)
{
    extern __shared__ unsigned dyn[];
    unsigned* AsU = dyn;
    unsigned* BsU = dyn + 64 * 68;
    float*    Hs  = (float*)(dyn + 2 * 64 * 68);
    __shared__ float redA[64][4];
    __shared__ float w0s[64], w1s[64];
    float* As = (float*)AsU;
    float* Ws = (float*)BsU;
    int tid = threadIdx.x;
    int row0 = blockIdx.x * 64;
    int wid = tid >> 5, lane = tid & 31;
    int g = lane >> 2, t = lane & 3;
    int r0 = (wid & 3) * 16, c0 = (wid >> 2) * 32;

    float acc[4][4] = {};
    for (int h = 0; h < 8; h++) {
        __syncthreads();
#pragma unroll
        for (int it = 0; it < 4; it++) {
            int idx = tid + it * 256;
            int r = idx >> 4, c4 = (idx & 15) * 4;
            cp16(&BsU[r * 68 + c4], &gG[(size_t)h * 4096 + r * 64 + c4]);
        }
        asm volatile("cp.async.commit_group;");
        if (tid < 64) {
            int node = row0 + tid;
            float l0 = g_lser[h * NNODE + node];
            float l1 = g_lser[(8 + h) * NNODE + node];
            float m = fmaxf(l0, l1);
            float e0 = __expf(l0 - m), e1 = __expf(l1 - m);
            float inv = 1.0f / (e0 + e1);
            w0s[tid] = e0 * inv;
            w1s[tid] = e1 * inv;
        }
        __syncthreads();
#pragma unroll
        for (int it = 0; it < 4; it++) {
            int idx = tid + it * 256;
            int r = idx >> 4, c4 = (idx & 15) * 4;
            int node = row0 + r;
            float4 o0 = *(const float4*)&g_outr[((size_t)h * NNODE + node) * 64 + c4];
            float4 o1 = *(const float4*)&g_outr[((size_t)(8 + h) * NNODE + node) * 64 + c4];
            float w0 = w0s[r], w1 = w1s[r];
            AsU[r * 68 + c4 + 0] = f2tf(w0 * o0.x + w1 * o1.x);
            AsU[r * 68 + c4 + 1] = f2tf(w0 * o0.y + w1 * o1.y);
            AsU[r * 68 + c4 + 2] = f2tf(w0 * o0.z + w1 * o1.z);
            AsU[r * 68 + c4 + 3] = f2tf(w0 * o0.w + w1 * o1.w);
        }
        asm volatile("cp.async.wait_group 0;");
        __syncthreads();
#pragma unroll
        for (int ks = 0; ks < 8; ks++) {
            int k0 = ks * 8;
            unsigned a0 = AsU[(r0 + g) * 68 + k0 + t];
            unsigned a1 = AsU[(r0 + g + 8) * 68 + k0 + t];
            unsigned a2 = AsU[(r0 + g) * 68 + k0 + t + 4];
            unsigned a3 = AsU[(r0 + g + 8) * 68 + k0 + t + 4];
#pragma unroll
            for (int nt = 0; nt < 4; nt++) {
                int n = c0 + nt * 8 + g;
                unsigned b0 = BsU[(k0 + t) * 68 + n];
                unsigned b1 = BsU[(k0 + t + 4) * 68 + n];
                mma_tf32(acc[nt], a0, a1, a2, a3, b0, b1);
            }
        }
    }
    __syncthreads();
#pragma unroll
    for (int nt = 0; nt < 4; nt++) {
#pragma unroll
        for (int cr = 0; cr < 4; cr++) {
            int rl = r0 + g + (cr >> 1) * 8;
            int ccol = c0 + nt * 8 + 2 * t + (cr & 1);
            Hs[rl * 68 + ccol] = acc[nt][cr] + ob[ccol] + g_h[(size_t)(row0 + rl) * 64 + ccol];
        }
    }
    __syncthreads();

    {
        int tr = tid >> 2, tp = tid & 3;
        float s = 0.f;
        for (int c = tp * 16; c < tp * 16 + 16; c++) s += Hs[tr * 68 + c];
        redA[tr][tp] = s;
        __syncthreads();
        float mu = (redA[tr][0] + redA[tr][1] + redA[tr][2] + redA[tr][3]) * (1.0f / 64.0f);
        __syncthreads();
        float vs = 0.f;
        for (int c = tp * 16; c < tp * 16 + 16; c++) {
            float d = Hs[tr * 68 + c] - mu;
            vs += d * d;
        }
        redA[tr][tp] = vs;
        __syncthreads();
        float var = (redA[tr][0] + redA[tr][1] + redA[tr][2] + redA[tr][3]) * (1.0f / 64.0f);
        float rs = rsqrtf(var + 1e-5f);
        for (int c = tp * 16; c < tp * 16 + 16; c++)
            As[tr * 68 + c] = (Hs[tr * 68 + c] - mu) * rs * lg2[c] + lb2[c];
    }
#pragma unroll
    for (int it = 0; it < 4; it++) {
        int idx = tid + it * 256;
        int r = idx >> 4, c4 = (idx & 15) * 4;
        *(float4*)&Ws[r * 68 + c4] = *(const float4*)&W1[(size_t)r * 64 + c4];
    }
    __syncthreads();

    int tm = tid >> 4, tn = tid & 15;
    float ac1[4][4] = {};
#pragma unroll 8
    for (int kk = 0; kk < 64; kk++) {
        float4 bv = *(const float4*)&Ws[kk * 68 + tn * 4];
        float4 av = make_float4(As[(tm * 4 + 0) * 68 + kk], As[(tm * 4 + 1) * 68 + kk],
                                As[(tm * 4 + 2) * 68 + kk], As[(tm * 4 + 3) * 68 + kk]);
        FMA16(av, bv, ac1)
    }
    __syncthreads();
#pragma unroll
    for (int ii = 0; ii < 4; ii++)
#pragma unroll
        for (int jj = 0; jj < 4; jj++)
            As[(tm * 4 + ii) * 68 + tn * 4 + jj] = fmaxf(ac1[ii][jj] + b1[tn * 4 + jj], 0.f);
#pragma unroll
    for (int it = 0; it < 4; it++) {
        int idx = tid + it * 256;
        int r = idx >> 4, c4 = (idx & 15) * 4;
        *(float4*)&Ws[r * 68 + c4] = *(const float4*)&W2[(size_t)r * 64 + c4];
    }
    __syncthreads();
    float ac2[4][4] = {};
#pragma unroll 8
    for (int kk = 0; kk < 64; kk++) {
        float4 bv = *(const float4*)&Ws[kk * 68 + tn * 4];
        float4 av = make_float4(As[(tm * 4 + 0) * 68 + kk], As[(tm * 4 + 1) * 68 + kk],
                                As[(tm * 4 + 2) * 68 + kk], As[(tm * 4 + 3) * 68 + kk]);
        FMA16(av, bv, ac2)
    }
    __syncthreads();
#pragma unroll
    for (int ii = 0; ii < 4; ii++) {
        int r = row0 + tm * 4 + ii;
        int rl = tm * 4 + ii;
#pragma unroll
        for (int jj = 0; jj < 4; jj++) {
            int c = tn * 4 + jj;
            float vv = ac2[ii][jj] + b2[c] + Hs[rl * 68 + c];
            g_h[(size_t)r * 64 + c] = vv;
            hist[(size_t)r * 320 + c] = vv;
            As[rl * 68 + c] = vv;
        }
    }
    if (lnn_g) {
        __syncthreads();
        ln64_smem(As, redA, lnn_g, lnn_b, (float*)g_xn, row0, tid);
    }
}

// ------------------------- scalar FFMA SGEMM (head: Wcat only) -------------------------
__global__ void __launch_bounds__(256) gemm_k(
    const float* __restrict__ A, const float* __restrict__ B, float* __restrict__ C,
    const float* __restrict__ bias, const float* __restrict__ resid,
    int M, int N, int K, int act)
{
    __shared__ float As[16][68];
    __shared__ float Bs[16][68];
    int tid = threadIdx.x;
    int row0 = blockIdx.x * 64, col0 = blockIdx.y * 64;
    int tm = tid >> 4, tn = tid & 15;
    int arow = tid >> 2, ac = tid & 3;
    int bk = tid >> 4, bn = tid & 15;
    float acc[4][4] = {};
    for (int k0 = 0; k0 < K; k0 += 16) {
        float4 a = *(const float4*)&A[(size_t)(row0 + arow) * K + k0 + ac * 4];
        As[ac * 4 + 0][arow] = a.x; As[ac * 4 + 1][arow] = a.y;
        As[ac * 4 + 2][arow] = a.z; As[ac * 4 + 3][arow] = a.w;
        int bcol = col0 + bn * 4;
        float4 bv = make_float4(0.f, 0.f, 0.f, 0.f);
        if (bcol < N) bv = *(const float4*)&B[(size_t)(k0 + bk) * N + bcol];
        *(float4*)&Bs[bk][bn * 4] = bv;
        __syncthreads();
#pragma unroll
        for (int kk = 0; kk < 16; kk++) {
            float4 av = *(const float4*)&As[kk][tm * 4];
            float4 bw = *(const float4*)&Bs[kk][tn * 4];
            FMA16(av, bw, acc)
        }
        __syncthreads();
    }
#pragma unroll
    for (int ii = 0; ii < 4; ii++) {
        int r = row0 + tm * 4 + ii;
#pragma unroll
        for (int jj = 0; jj < 4; jj++) {
            int ccol = col0 + tn * 4 + jj;
            if (ccol < N) {
                float vv = acc[ii][jj];
                if (bias) vv += bias[ccol];
                if (act == 1) vv = fmaxf(vv, 0.f);
                else if (act == 2) vv = tanhf(vv);
                if (resid) vv += resid[(size_t)r * N + ccol];
                C[(size_t)r * N + ccol] = vv;
            }
        }
    }
}

// ------------------------- fused m1 GEMM + LN256 + tanh + partial means -------------------------
__global__ void __launch_bounds__(256) m1ln_k(
    const float* __restrict__ t0, const float* __restrict__ m1w, const float* __restrict__ m1b,
    const float* __restrict__ lng, const float* __restrict__ lnb)
{
    __shared__ float As[64 * 36];    // t0 tile [64][32] padded
    __shared__ float Ws[32 * 260];   // m1w [32][256] padded; reused as col-partials [16][256]
    __shared__ float redr[64 * 16];  // per-row partials
    int tid = threadIdx.x;
    int row0 = blockIdx.x * 64;
#pragma unroll
    for (int it = 0; it < 2; it++) {
        int e = tid + it * 256;                 // 0..511 float4 = 2048 floats
        int rr = e >> 3, cc = (e & 7) * 4;
        float4 v = *(const float4*)&t0[(size_t)(row0 + rr) * 32 + cc];
        As[rr * 36 + cc + 0] = v.x; As[rr * 36 + cc + 1] = v.y;
        As[rr * 36 + cc + 2] = v.z; As[rr * 36 + cc + 3] = v.w;
    }
#pragma unroll
    for (int it = 0; it < 8; it++) {
        int e = tid + it * 256;                 // 0..2047 float4 = 8192 floats
        int k = e >> 6, n4 = (e & 63) * 4;
        *(float4*)&Ws[k * 260 + n4] = *(const float4*)&m1w[(size_t)k * 256 + n4];
    }
    __syncthreads();
    int tm = tid >> 4, tn = tid & 15;          // rows tm*4..+3, cols tn*16..+15
    float u[4][16];
#pragma unroll
    for (int ii = 0; ii < 4; ii++)
#pragma unroll
        for (int jj = 0; jj < 16; jj++) u[ii][jj] = m1b[tn * 16 + jj];
    for (int kk = 0; kk < 32; kk++) {
        float a0 = As[(tm * 4 + 0) * 36 + kk], a1 = As[(tm * 4 + 1) * 36 + kk];
        float a2 = As[(tm * 4 + 2) * 36 + kk], a3 = As[(tm * 4 + 3) * 36 + kk];
#pragma unroll
        for (int jj = 0; jj < 16; jj++) {
            float b = Ws[kk * 260 + tn * 16 + jj];
            u[0][jj] += a0 * b; u[1][jj] += a1 * b;
            u[2][jj] += a2 * b; u[3][jj] += a3 * b;
        }
    }
    __syncthreads();   // GEMM done everywhere; Ws free for reuse

    // LN over 256 per row: row sums
    float mu[4], rs[4];
#pragma unroll
    for (int ii = 0; ii < 4; ii++) {
        float s = 0.f;
#pragma unroll
        for (int jj = 0; jj < 16; jj++) s += u[ii][jj];
        redr[(tm * 4 + ii) * 16 + tn] = s;
    }
    __syncthreads();
#pragma unroll
    for (int ii = 0; ii < 4; ii++) {
        float s = 0.f;
        for (int q = 0; q < 16; q++) s += redr[(tm * 4 + ii) * 16 + q];
        mu[ii] = s * (1.0f / 256.0f);
    }
    __syncthreads();
#pragma unroll
    for (int ii = 0; ii < 4; ii++) {
        float vs = 0.f;
#pragma unroll
        for (int jj = 0; jj < 16; jj++) {
            float d = u[ii][jj] - mu[ii];
            vs += d * d;
        }
        redr[(tm * 4 + ii) * 16 + tn] = vs;
    }
    __syncthreads();
#pragma unroll
    for (int ii = 0; ii < 4; ii++) {
        float vs = 0.f;
        for (int q = 0; q < 16; q++) vs += redr[(tm * 4 + ii) * 16 + q];
        rs[ii] = rsqrtf(vs * (1.0f / 256.0f) + 1e-5f);
    }
    // u2 = tanh(LN) and column partials (4 rows per thread)
#pragma unroll
    for (int jj = 0; jj < 16; jj++) {
        int c = tn * 16 + jj;
        float gc = lng[c], bc = lnb[c];
        float s = 0.f;
#pragma unroll
        for (int ii = 0; ii < 4; ii++)
            s += tanhf((u[ii][jj] - mu[ii]) * rs[ii] * gc + bc);
        Ws[tm * 256 + c] = s;     // colred[tm][c]
    }
    __syncthreads();
    {   // part2: sum 16 row-groups per column (deterministic)
        float s = 0.f;
        for (int q = 0; q < 16; q++) s += Ws[q * 256 + tid];
        g_part2[(size_t)blockIdx.x * 256 + tid] = s;
    }
    if (tid < 32) {   // part0: t0 column sums over 64 rows
        float s = 0.f;
        for (int r = 0; r < 64; r++) s += As[r * 36 + tid];
        g_part0[(size_t)blockIdx.x * 32 + tid] = s;
    }
}

// ------------------------- final: means -> m2 -> project -------------------------
__global__ void final_k(const float* __restrict__ m2w, const float* __restrict__ m2b,
                        const float* __restrict__ pw, const float* __restrict__ pb,
                        float* __restrict__ out)
{
    __shared__ float mean2[256];
    __shared__ float mean0[32];
    __shared__ float vv[32];
    int t = threadIdx.x;
    {
        float s = 0.f;
        for (int b = 0; b < 256; b++) s += g_part2[(size_t)b * 256 + t];
        mean2[t] = s * (1.0f / 16384.0f);
    }
    if (t < 32) {
        float s = 0.f;
        for (int b = 0; b < 256; b++) s += g_part0[(size_t)b * 32 + t];
        mean0[t] = s * (1.0f / 16384.0f);
    }
    __syncthreads();
    if (t < 32) {
        float v = mean0[t] + m2b[t];
        for (int c = 0; c < 256; c++) v += mean2[c] * m2w[c * 32 + t];
        vv[t] = v;
    }
    __syncthreads();
    if (t < 32) {
        float s = pb[t];
        for (int c = 0; c < 32; c++) s += vv[c] * pw[c * 32 + t];
        out[t] = s;
    }
}

// ------------------------- host orchestration -------------------------
extern "C" void kernel_launch(void* const* d_in, const int* in_sizes, int n_in,
                              void* d_out, int out_size)
{
    const float* x      = (const float*)d_in[0];
    const float* coords = (const float*)d_in[1];
    const float* regions= (const float*)d_in[3];
    const float* fe_w1  = (const float*)d_in[4];
    const float* fe_b1  = (const float*)d_in[5];
    const float* fe_w2  = (const float*)d_in[6];
    const float* fe_b2  = (const float*)d_in[7];
    const float* ln1_g  = (const float*)d_in[8];
    const float* ln1_b  = (const float*)d_in[9];
    const float* wq     = (const float*)d_in[10];
    const float* wk     = (const float*)d_in[11];
    const float* wv     = (const float*)d_in[12];
    const float* wrpe   = (const float*)d_in[13];
    const float* ow     = (const float*)d_in[14];
    const float* ob     = (const float*)d_in[15];
    const float* ln2_g  = (const float*)d_in[16];
    const float* ln2_b  = (const float*)d_in[17];
    const float* f1w    = (const float*)d_in[18];
    const float* f1b    = (const float*)d_in[19];
    const float* f2w    = (const float*)d_in[20];
    const float* f2b    = (const float*)d_in[21];
    const float* Wcat   = (const float*)d_in[22];
    const float* m1w    = (const float*)d_in[23];
    const float* m1b    = (const float*)d_in[24];
    const float* mlng   = (const float*)d_in[25];
    const float* mlnb   = (const float*)d_in[26];
    const float* m2w    = (const float*)d_in[27];
    const float* m2b    = (const float*)d_in[28];
    const float* pw     = (const float*)d_in[29];
    const float* pb     = (const float*)d_in[30];
    float* out = (float*)d_out;

    cudaFuncSetAttribute(epi_k, cudaFuncAttributeMaxDynamicSharedMemorySize, 52224);

    float *p_hist, *p_t0, *p_w2, *p_M, *p_G;
    int *p_rhist, *p_rbase, *p_bhist, *p_bbase;
    cudaGetSymbolAddress((void**)&p_hist, g_hist);
    cudaGetSymbolAddress((void**)&p_t0,   g_t0);
    cudaGetSymbolAddress((void**)&p_w2,   g_W2);
    cudaGetSymbolAddress((void**)&p_M,    g_M);
    cudaGetSymbolAddress((void**)&p_G,    g_G);
    cudaGetSymbolAddress((void**)&p_rhist, r_hist);
    cudaGetSymbolAddress((void**)&p_rbase, r_base);
    cudaGetSymbolAddress((void**)&p_bhist, b_hist);
    cudaGetSymbolAddress((void**)&p_bbase, b_base);

    const int M = NNODE;

    // ---- bucket ordering via counting sorts (R12 config) ----
    zero_k<<<512, 256>>>();
    rank_hist_k<<<dim3(64, 2), 256>>>(coords);
    scan_k<<<2, 1024>>>(p_rhist, p_rbase, NNODE, NNODE);
    rank_place_k<<<dim3(64, 2), 256>>>(coords);
    rank_rank_k<<<dim3(64, 2), 256>>>(coords);
    key_k<<<dim3(64, 16), 256>>>(regions);
    scan_k<<<16, 1024>>>(p_bhist, p_bbase, KBINS, KBINS);
    bucket_place_k<<<dim3(64, 16), 256>>>();
    bucket_pos_k<<<dim3(64, 16), 256>>>();
    w2all_k<<<4, 128>>>(wrpe);
    mh_k<<<32, 256>>>(wq, wk);
    gw_k<<<32, 256>>>(wv, ow);

    // feat encoder + LN1(layer 0)
    ffe_k<<<256, 256>>>(x, fe_w1, fe_b1, fe_w2, fe_b2, ln1_g, ln1_b);

    for (int l = 0; l < 4; l++) {
        tq_k<<<dim3(256, 8), 256>>>(p_M + (size_t)l * 8 * 4096);
        attn_k<<<dim3(256, 8, 2), 256>>>(coords, p_w2 + l * 16);
        const float* nlg = (l < 3) ? (ln1_g + (l + 1) * 64) : nullptr;
        const float* nlb = (l < 3) ? (ln1_b + (l + 1) * 64) : nullptr;
        epi_k<<<256, 256, 52224>>>(p_G + (size_t)l * 8 * 4096, ob + l * 64,
                                   ln2_g + l * 64, ln2_b + l * 64,
                                   f1w + (size_t)l * 64 * 64, f1b + l * 64,
                                   f2w + (size_t)l * 64 * 64, f2b + l * 64,
                                   p_hist + (l + 1) * 64, nlg, nlb);
    }

    // head: t0 = tanh(hist @ Wcat); mean via linearity of the final layers
    gemm_k<<<dim3(256, 1), 256>>>(p_hist, Wcat, p_t0, nullptr, nullptr, M, 32, 320, 2);
    m1ln_k<<<256, 256>>>(p_t0, m1w, m1b, mlng, mlnb);
    final_k<<<1, 256>>>(m2w, m2b, pw, pb, out);
}